// round 7
// baseline (speedup 1.0000x reference)
#include <cuda_runtime.h>
#include <cuda_bf16.h>
#include <float.h>

#define NB    16384   // total points = B*N
#define NPTS  2048
#define BATCH 8
#define KNN   20
#define NEG_SLOPE 0.2f

// ---------------- scratch (device globals; no runtime allocation) ----------
__device__ float g_X1[NB * 64];
__device__ float g_X2[NB * 64];
__device__ float g_X3[NB * 128];
__device__ float g_X4[NB * 256];
__device__ float g_PC[NB * 512];                 // [P | C], max 2*cout = 512
__device__ float g_G[(size_t)BATCH * NPTS * NPTS]; // Gram matrices (134 MB)
__device__ float g_xx[NB];
__device__ int   g_idx[NB * KNN];
__device__ float g_Wcomb[128 * 512];             // max cin*2cout
__device__ float g_cat[NB * 512];

// ---------------- squared norms (warp per row) ------------------------------
__global__ void xx_kernel(const float* __restrict__ X, float* __restrict__ xx, int C) {
    int gw = (blockIdx.x * blockDim.x + threadIdx.x) >> 5;
    int lane = threadIdx.x & 31;
    if (gw >= NB) return;
    const float* row = X + (size_t)gw * C;
    float s = 0.f;
    for (int c = lane; c < C; c += 32) { float v = row[c]; s += v * v; }
    #pragma unroll
    for (int o = 16; o > 0; o >>= 1) s += __shfl_xor_sync(0xFFFFFFFFu, s, o);
    if (lane == 0) xx[gw] = s;
}

// ---------------- batched Gram: G_b = X_b @ X_b^T ---------------------------
__global__ void __launch_bounds__(256) gemm_xxt(const float* __restrict__ X,
                                                float* __restrict__ G, int Kdim) {
    __shared__ float As[16][68];
    __shared__ float Bs[16][68];
    int b = blockIdx.z;
    const float* A = X + (size_t)b * NPTS * Kdim;
    float* Gb = G + (size_t)b * NPTS * NPTS;
    int tid = threadIdx.x;
    int m0 = blockIdx.y * 64, n0 = blockIdx.x * 64;
    int tm = tid >> 4, tn = tid & 15;
    float acc[4][4] = {};
    for (int k0 = 0; k0 < Kdim; k0 += 16) {
        #pragma unroll
        for (int i = 0; i < 4; i++) {
            int idx = tid + i * 256;
            int k = idx & 15, r = idx >> 4;
            bool kin = (k0 + k) < Kdim;
            As[k][r] = kin ? A[(size_t)(m0 + r) * Kdim + k0 + k] : 0.f;
            Bs[k][r] = kin ? A[(size_t)(n0 + r) * Kdim + k0 + k] : 0.f;
        }
        __syncthreads();
        #pragma unroll
        for (int k = 0; k < 16; k++) {
            float4 af = *(const float4*)&As[k][tm << 2];
            float4 bf = *(const float4*)&Bs[k][tn << 2];
            float a_[4] = {af.x, af.y, af.z, af.w};
            float b_[4] = {bf.x, bf.y, bf.z, bf.w};
            #pragma unroll
            for (int ii = 0; ii < 4; ii++)
                #pragma unroll
                for (int jj = 0; jj < 4; jj++)
                    acc[ii][jj] = fmaf(a_[ii], b_[jj], acc[ii][jj]);
        }
        __syncthreads();
    }
    #pragma unroll
    for (int i = 0; i < 4; i++) {
        float4 v = make_float4(acc[i][0], acc[i][1], acc[i][2], acc[i][3]);
        *(float4*)&Gb[(size_t)(m0 + tm * 4 + i) * NPTS + n0 + tn * 4] = v;
    }
}

// ---------------- generic C = A(MxK) @ B(KxN) -------------------------------
__global__ void __launch_bounds__(256) gemm_nn(const float* __restrict__ A,
                                               const float* __restrict__ B,
                                               float* __restrict__ Cout,
                                               int N, int Kdim) {
    __shared__ float As[16][68];
    __shared__ float Bs[16][68];
    int tid = threadIdx.x;
    int m0 = blockIdx.y * 64, n0 = blockIdx.x * 64;
    int tm = tid >> 4, tn = tid & 15;
    float acc[4][4] = {};
    for (int k0 = 0; k0 < Kdim; k0 += 16) {
        #pragma unroll
        for (int i = 0; i < 4; i++) {
            int idx = tid + i * 256;
            int ka = idx & 15, r = idx >> 4;
            As[ka][r] = (k0 + ka < Kdim) ? A[(size_t)(m0 + r) * Kdim + k0 + ka] : 0.f;
            int kb = idx >> 6, n = idx & 63;
            Bs[kb][n] = (k0 + kb < Kdim) ? B[(size_t)(k0 + kb) * N + n0 + n] : 0.f;
        }
        __syncthreads();
        #pragma unroll
        for (int k = 0; k < 16; k++) {
            float4 af = *(const float4*)&As[k][tm << 2];
            float4 bf = *(const float4*)&Bs[k][tn << 2];
            float a_[4] = {af.x, af.y, af.z, af.w};
            float b_[4] = {bf.x, bf.y, bf.z, bf.w};
            #pragma unroll
            for (int ii = 0; ii < 4; ii++)
                #pragma unroll
                for (int jj = 0; jj < 4; jj++)
                    acc[ii][jj] = fmaf(a_[ii], b_[jj], acc[ii][jj]);
        }
        __syncthreads();
    }
    #pragma unroll
    for (int i = 0; i < 4; i++) {
        float4 v = make_float4(acc[i][0], acc[i][1], acc[i][2], acc[i][3]);
        *(float4*)&Cout[(size_t)(m0 + tm * 4 + i) * N + n0 + tn * 4] = v;
    }
}

// ---------------- final layer: out = lrelu(cat@W5 * g + b), transposed ------
__global__ void __launch_bounds__(256) gemm_w5(const float* __restrict__ A,
                                               const float* __restrict__ B,
                                               const float* __restrict__ g,
                                               const float* __restrict__ bias,
                                               float* __restrict__ out,
                                               int N, int Kdim) {
    __shared__ float As[16][68];
    __shared__ float Bs[16][68];
    int tid = threadIdx.x;
    int m0 = blockIdx.y * 64, n0 = blockIdx.x * 64;
    int tm = tid >> 4, tn = tid & 15;
    float acc[4][4] = {};
    for (int k0 = 0; k0 < Kdim; k0 += 16) {
        #pragma unroll
        for (int i = 0; i < 4; i++) {
            int idx = tid + i * 256;
            int ka = idx & 15, r = idx >> 4;
            As[ka][r] = (k0 + ka < Kdim) ? A[(size_t)(m0 + r) * Kdim + k0 + ka] : 0.f;
            int kb = idx >> 6, n = idx & 63;
            Bs[kb][n] = (k0 + kb < Kdim) ? B[(size_t)(k0 + kb) * N + n0 + n] : 0.f;
        }
        __syncthreads();
        #pragma unroll
        for (int k = 0; k < 16; k++) {
            float4 af = *(const float4*)&As[k][tm << 2];
            float4 bf = *(const float4*)&Bs[k][tn << 2];
            float a_[4] = {af.x, af.y, af.z, af.w};
            float b_[4] = {bf.x, bf.y, bf.z, bf.w};
            #pragma unroll
            for (int ii = 0; ii < 4; ii++)
                #pragma unroll
                for (int jj = 0; jj < 4; jj++)
                    acc[ii][jj] = fmaf(a_[ii], b_[jj], acc[ii][jj]);
        }
        __syncthreads();
    }
    int mrow = m0 + tm * 4;
    int bidx = mrow >> 11;        // batch
    int npt  = mrow & 2047;       // point within batch (multiple of 4)
    #pragma unroll
    for (int j = 0; j < 4; j++) {
        int col = n0 + tn * 4 + j;
        float gd = g[col], bd = bias[col];
        float4 v;
        float h0 = fmaf(acc[0][j], gd, bd); v.x = h0 >= 0.f ? h0 : NEG_SLOPE * h0;
        float h1 = fmaf(acc[1][j], gd, bd); v.y = h1 >= 0.f ? h1 : NEG_SLOPE * h1;
        float h2 = fmaf(acc[2][j], gd, bd); v.z = h2 >= 0.f ? h2 : NEG_SLOPE * h2;
        float h3 = fmaf(acc[3][j], gd, bd); v.w = h3 >= 0.f ? h3 : NEG_SLOPE * h3;
        *(float4*)&out[((size_t)bidx * 1024 + col) * NPTS + npt] = v;
    }
}

// ---------------- top-20 selection per row ----------------------------------
__global__ void __launch_bounds__(256) topk_kernel(const float* __restrict__ G,
                                                   const float* __restrict__ xx,
                                                   int* __restrict__ idxout) {
    __shared__ float negd[NPTS];
    __shared__ float rv[256];
    __shared__ int   ri[256];
    int row = blockIdx.x;
    int b = row >> 11;
    int tid = threadIdx.x;
    const float* Grow = G + (size_t)row * NPTS;
    float xxi = xx[row];
    const float* xxb = xx + b * NPTS;
    for (int j = tid; j < NPTS; j += 256)
        negd[j] = 2.f * Grow[j] - xxi - xxb[j];
    __syncthreads();
    for (int r = 0; r < KNN; r++) {
        float bv = -FLT_MAX; int bi = NPTS;
        for (int j = tid; j < NPTS; j += 256) {
            float v = negd[j];
            if (v > bv || (v == bv && j < bi)) { bv = v; bi = j; }
        }
        rv[tid] = bv; ri[tid] = bi;
        __syncthreads();
        #pragma unroll
        for (int s = 128; s > 0; s >>= 1) {
            if (tid < s) {
                float ov = rv[tid + s]; int oi = ri[tid + s];
                if (ov > rv[tid] || (ov == rv[tid] && oi < ri[tid])) { rv[tid] = ov; ri[tid] = oi; }
            }
            __syncthreads();
        }
        if (tid == 0) {
            idxout[row * KNN + r] = b * NPTS + ri[0];   // global point id
            negd[ri[0]] = -FLT_MAX;
        }
        __syncthreads();
    }
}

// ---------------- gather + max/min over neighbors + epilogue ----------------
__global__ void gathermax_kernel(const float* __restrict__ PC,
                                 const int* __restrict__ idx,
                                 const float* __restrict__ g,
                                 const float* __restrict__ bias,
                                 float* __restrict__ Xout, int cout) {
    __shared__ int sidx[KNN];
    int n = blockIdx.x, d = threadIdx.x;
    if (threadIdx.x < KNN) sidx[threadIdx.x] = idx[n * KNN + threadIdx.x];
    __syncthreads();
    int ld = cout * 2;
    float mx = -FLT_MAX, mn = FLT_MAX;
    #pragma unroll
    for (int k = 0; k < KNN; k++) {
        float v = PC[(size_t)sidx[k] * ld + d];
        mx = fmaxf(mx, v); mn = fminf(mn, v);
    }
    float Cc = PC[(size_t)n * ld + cout + d];
    float gd = g[d], bd = bias[d];
    float z = (gd >= 0.f ? mx : mn) + Cc;
    float h = fmaf(gd, z, bd);
    Xout[(size_t)n * cout + d] = h >= 0.f ? h : NEG_SLOPE * h;
}

// ---------------- combined weight: [W_a | W_b - W_a] ------------------------
__global__ void wcomb_kernel(const float* __restrict__ W, float* __restrict__ Wc,
                             int cin, int cout) {
    int i = blockIdx.x * 256 + threadIdx.x;
    int tot = cin * 2 * cout;
    if (i >= tot) return;
    int twoc = 2 * cout;
    int c = i / twoc, j = i - c * twoc;
    float v;
    if (j < cout) v = W[c * cout + j];
    else { int dd = j - cout; v = W[(cin + c) * cout + dd] - W[c * cout + dd]; }
    Wc[i] = v;
}

// ---------------- concat x1..x4 ---------------------------------------------
__global__ void cat_kernel(const float* __restrict__ a, const float* __restrict__ b,
                           const float* __restrict__ c, const float* __restrict__ d,
                           float* __restrict__ o) {
    int i = blockIdx.x * 256 + threadIdx.x;   // total NB*512
    int n = i >> 9, ch = i & 511;
    float v;
    if (ch < 64)        v = a[(size_t)n * 64  + ch];
    else if (ch < 128)  v = b[(size_t)n * 64  + ch - 64];
    else if (ch < 256)  v = c[(size_t)n * 128 + ch - 128];
    else                v = d[(size_t)n * 256 + ch - 256];
    o[i] = v;
}

// ---------------- host launch ------------------------------------------------
extern "C" void kernel_launch(void* const* d_in, const int* in_sizes, int n_in,
                              void* d_out, int out_size) {
    (void)in_sizes; (void)n_in; (void)out_size;
    const float* pts = (const float*)d_in[0];
    const float* W[5]; const float* gg[5]; const float* bb[5];
    for (int i = 0; i < 5; i++) {
        W[i]  = (const float*)d_in[1 + 3 * i];
        gg[i] = (const float*)d_in[2 + 3 * i];
        bb[i] = (const float*)d_in[3 + 3 * i];
    }
    float* out = (float*)d_out;

    float *X1, *X2, *X3, *X4, *PC, *G, *XX, *WC, *CAT; int* IDX;
    cudaGetSymbolAddress((void**)&X1,  g_X1);
    cudaGetSymbolAddress((void**)&X2,  g_X2);
    cudaGetSymbolAddress((void**)&X3,  g_X3);
    cudaGetSymbolAddress((void**)&X4,  g_X4);
    cudaGetSymbolAddress((void**)&PC,  g_PC);
    cudaGetSymbolAddress((void**)&G,   g_G);
    cudaGetSymbolAddress((void**)&XX,  g_xx);
    cudaGetSymbolAddress((void**)&WC,  g_Wcomb);
    cudaGetSymbolAddress((void**)&CAT, g_cat);
    cudaGetSymbolAddress((void**)&IDX, g_idx);

    struct L { const float* Xin; int cin, cout; float* Xout; };
    L layers[4] = {
        { pts, 3,   64,  X1 },
        { X1,  64,  64,  X2 },
        { X2,  64,  128, X3 },
        { X3,  128, 256, X4 },
    };
    for (int li = 0; li < 4; li++) {
        const L& l = layers[li];
        xx_kernel<<<NB / 8, 256>>>(l.Xin, XX, l.cin);
        gemm_xxt<<<dim3(NPTS / 64, NPTS / 64, BATCH), 256>>>(l.Xin, G, l.cin);
        topk_kernel<<<NB, 256>>>(G, XX, IDX);
        int tot = l.cin * 2 * l.cout;
        wcomb_kernel<<<(tot + 255) / 256, 256>>>(W[li], WC, l.cin, l.cout);
        gemm_nn<<<dim3((2 * l.cout) / 64, NB / 64), 256>>>(l.Xin, WC, PC, 2 * l.cout, l.cin);
        gathermax_kernel<<<NB, l.cout>>>(PC, IDX, gg[li], bb[li], l.Xout, l.cout);
    }
    cat_kernel<<<(NB * 512) / 256, 256>>>(X1, X2, X3, X4, CAT);
    gemm_w5<<<dim3(1024 / 64, NB / 64), 256>>>(CAT, W[4], gg[4], bb[4], out, 1024, 512);
}

// round 8
// speedup vs baseline: 1.1943x; 1.1943x over previous
#include <cuda_runtime.h>
#include <cuda_bf16.h>
#include <float.h>

#define NB    16384   // total points = B*N
#define NPTS  2048
#define BATCH 8
#define KNN   20
#define NEG_SLOPE 0.2f

#define BM 128
#define BN 128
#define BK 8

// ---------------- scratch (device globals; no runtime allocation) ----------
__device__ float g_X1[NB * 64];
__device__ float g_X2[NB * 64];
__device__ float g_X3[NB * 128];
__device__ float g_X4[NB * 256];
__device__ float g_PC[NB * 512];                   // [P | C], max 2*cout = 512
__device__ float g_G[(size_t)BATCH * NPTS * NPTS]; // Gram matrices
__device__ float g_xx[NB];
__device__ int   g_idx[NB * KNN];
__device__ float g_Wcomb[128 * 512];               // max cin*2cout
__device__ float g_cat[NB * 512];

// ---------------- squared norms (warp per row) ------------------------------
__global__ void xx_kernel(const float* __restrict__ X, float* __restrict__ xx, int C) {
    int gw = (blockIdx.x * blockDim.x + threadIdx.x) >> 5;
    int lane = threadIdx.x & 31;
    if (gw >= NB) return;
    const float* row = X + (size_t)gw * C;
    float s = 0.f;
    for (int c = lane; c < C; c += 32) { float v = row[c]; s += v * v; }
    #pragma unroll
    for (int o = 16; o > 0; o >>= 1) s += __shfl_xor_sync(0xFFFFFFFFu, s, o);
    if (lane == 0) xx[gw] = s;
}

// ---------------- batched Gram: G_b = X_b @ X_b^T  (128x128x8, dbl-buffered) -
__global__ void __launch_bounds__(256, 2) gram_gemm(const float* __restrict__ X,
                                                    float* __restrict__ G, int Kdim) {
    __shared__ float As[2][BK][BM + 4];
    __shared__ float Bs[2][BK][BN + 4];
    int b = blockIdx.z;
    const float* A = X + (size_t)b * NPTS * Kdim;
    float* Gb = G + (size_t)b * NPTS * NPTS;
    int tid = threadIdx.x;
    int m0 = blockIdx.y * BM, n0 = blockIdx.x * BN;
    int tm = tid >> 4, tn = tid & 15;
    int la_m = tid >> 3, la_k = tid & 7;
    float acc[8][8] = {};
    float ra[4], rb[4];
    int kIters = (Kdim + BK - 1) / BK;
    #pragma unroll
    for (int i = 0; i < 4; i++) {
        int m = la_m + 32 * i;
        ra[i] = (la_k < Kdim) ? A[(size_t)(m0 + m) * Kdim + la_k] : 0.f;
        rb[i] = (la_k < Kdim) ? A[(size_t)(n0 + m) * Kdim + la_k] : 0.f;
    }
    #pragma unroll
    for (int i = 0; i < 4; i++) {
        As[0][la_k][la_m + 32 * i] = ra[i];
        Bs[0][la_k][la_m + 32 * i] = rb[i];
    }
    __syncthreads();
    int buf = 0;
    for (int it = 0; it < kIters; ++it) {
        if (it + 1 < kIters) {
            int kg = (it + 1) * BK + la_k;
            #pragma unroll
            for (int i = 0; i < 4; i++) {
                int m = la_m + 32 * i;
                ra[i] = (kg < Kdim) ? A[(size_t)(m0 + m) * Kdim + kg] : 0.f;
                rb[i] = (kg < Kdim) ? A[(size_t)(n0 + m) * Kdim + kg] : 0.f;
            }
        }
        #pragma unroll
        for (int k = 0; k < BK; k++) {
            float4 a0 = *(const float4*)&As[buf][k][tm * 8];
            float4 a1 = *(const float4*)&As[buf][k][tm * 8 + 4];
            float4 b0 = *(const float4*)&Bs[buf][k][tn * 8];
            float4 b1 = *(const float4*)&Bs[buf][k][tn * 8 + 4];
            float av[8] = {a0.x, a0.y, a0.z, a0.w, a1.x, a1.y, a1.z, a1.w};
            float bv[8] = {b0.x, b0.y, b0.z, b0.w, b1.x, b1.y, b1.z, b1.w};
            #pragma unroll
            for (int ii = 0; ii < 8; ii++)
                #pragma unroll
                for (int jj = 0; jj < 8; jj++)
                    acc[ii][jj] = fmaf(av[ii], bv[jj], acc[ii][jj]);
        }
        if (it + 1 < kIters) {
            #pragma unroll
            for (int i = 0; i < 4; i++) {
                As[buf ^ 1][la_k][la_m + 32 * i] = ra[i];
                Bs[buf ^ 1][la_k][la_m + 32 * i] = rb[i];
            }
        }
        __syncthreads();
        buf ^= 1;
    }
    #pragma unroll
    for (int ii = 0; ii < 8; ii++) {
        size_t p = (size_t)(m0 + tm * 8 + ii) * NPTS + n0 + tn * 8;
        *(float4*)&Gb[p]     = make_float4(acc[ii][0], acc[ii][1], acc[ii][2], acc[ii][3]);
        *(float4*)&Gb[p + 4] = make_float4(acc[ii][4], acc[ii][5], acc[ii][6], acc[ii][7]);
    }
}

// ---------------- generic C = A(MxK) @ B(KxN), N multiple of 128 ------------
__global__ void __launch_bounds__(256, 2) gemm_nn(const float* __restrict__ A,
                                                  const float* __restrict__ B,
                                                  float* __restrict__ Cout,
                                                  int N, int Kdim) {
    __shared__ float As[2][BK][BM + 4];
    __shared__ float Bs[2][BK][BN + 4];
    int tid = threadIdx.x;
    int m0 = blockIdx.y * BM, n0 = blockIdx.x * BN;
    int tm = tid >> 4, tn = tid & 15;
    int la_m = tid >> 3, la_k = tid & 7;
    int lb_k = tid >> 7, lb_n = tid & 127;
    float acc[8][8] = {};
    float ra[4], rb[4];
    int kIters = (Kdim + BK - 1) / BK;
    #pragma unroll
    for (int i = 0; i < 4; i++) {
        int m = la_m + 32 * i;
        ra[i] = (la_k < Kdim) ? A[(size_t)(m0 + m) * Kdim + la_k] : 0.f;
        int kb = lb_k + 2 * i;
        rb[i] = (kb < Kdim) ? B[(size_t)kb * N + n0 + lb_n] : 0.f;
    }
    #pragma unroll
    for (int i = 0; i < 4; i++) {
        As[0][la_k][la_m + 32 * i] = ra[i];
        Bs[0][lb_k + 2 * i][lb_n] = rb[i];
    }
    __syncthreads();
    int buf = 0;
    for (int it = 0; it < kIters; ++it) {
        if (it + 1 < kIters) {
            int k0n = (it + 1) * BK;
            #pragma unroll
            for (int i = 0; i < 4; i++) {
                int m = la_m + 32 * i;
                int ka = k0n + la_k;
                ra[i] = (ka < Kdim) ? A[(size_t)(m0 + m) * Kdim + ka] : 0.f;
                int kb = k0n + lb_k + 2 * i;
                rb[i] = (kb < Kdim) ? B[(size_t)kb * N + n0 + lb_n] : 0.f;
            }
        }
        #pragma unroll
        for (int k = 0; k < BK; k++) {
            float4 a0 = *(const float4*)&As[buf][k][tm * 8];
            float4 a1 = *(const float4*)&As[buf][k][tm * 8 + 4];
            float4 b0 = *(const float4*)&Bs[buf][k][tn * 8];
            float4 b1 = *(const float4*)&Bs[buf][k][tn * 8 + 4];
            float av[8] = {a0.x, a0.y, a0.z, a0.w, a1.x, a1.y, a1.z, a1.w};
            float bv[8] = {b0.x, b0.y, b0.z, b0.w, b1.x, b1.y, b1.z, b1.w};
            #pragma unroll
            for (int ii = 0; ii < 8; ii++)
                #pragma unroll
                for (int jj = 0; jj < 8; jj++)
                    acc[ii][jj] = fmaf(av[ii], bv[jj], acc[ii][jj]);
        }
        if (it + 1 < kIters) {
            #pragma unroll
            for (int i = 0; i < 4; i++) {
                As[buf ^ 1][la_k][la_m + 32 * i] = ra[i];
                Bs[buf ^ 1][lb_k + 2 * i][lb_n] = rb[i];
            }
        }
        __syncthreads();
        buf ^= 1;
    }
    #pragma unroll
    for (int ii = 0; ii < 8; ii++) {
        size_t p = (size_t)(m0 + tm * 8 + ii) * N + n0 + tn * 8;
        *(float4*)&Cout[p]     = make_float4(acc[ii][0], acc[ii][1], acc[ii][2], acc[ii][3]);
        *(float4*)&Cout[p + 4] = make_float4(acc[ii][4], acc[ii][5], acc[ii][6], acc[ii][7]);
    }
}

// ---------------- final layer: out = lrelu(cat@W5 * g + b), transposed ------
__global__ void __launch_bounds__(256, 2) gemm_w5(const float* __restrict__ A,
                                                  const float* __restrict__ B,
                                                  const float* __restrict__ g,
                                                  const float* __restrict__ bias,
                                                  float* __restrict__ out,
                                                  int N, int Kdim) {
    __shared__ float As[2][BK][BM + 4];
    __shared__ float Bs[2][BK][BN + 4];
    int tid = threadIdx.x;
    int m0 = blockIdx.y * BM, n0 = blockIdx.x * BN;
    int tm = tid >> 4, tn = tid & 15;
    int la_m = tid >> 3, la_k = tid & 7;
    int lb_k = tid >> 7, lb_n = tid & 127;
    float acc[8][8] = {};
    float ra[4], rb[4];
    int kIters = Kdim / BK;
    #pragma unroll
    for (int i = 0; i < 4; i++) {
        int m = la_m + 32 * i;
        ra[i] = A[(size_t)(m0 + m) * Kdim + la_k];
        rb[i] = B[(size_t)(lb_k + 2 * i) * N + n0 + lb_n];
    }
    #pragma unroll
    for (int i = 0; i < 4; i++) {
        As[0][la_k][la_m + 32 * i] = ra[i];
        Bs[0][lb_k + 2 * i][lb_n] = rb[i];
    }
    __syncthreads();
    int buf = 0;
    for (int it = 0; it < kIters; ++it) {
        if (it + 1 < kIters) {
            int k0n = (it + 1) * BK;
            #pragma unroll
            for (int i = 0; i < 4; i++) {
                int m = la_m + 32 * i;
                ra[i] = A[(size_t)(m0 + m) * Kdim + k0n + la_k];
                rb[i] = B[(size_t)(k0n + lb_k + 2 * i) * N + n0 + lb_n];
            }
        }
        #pragma unroll
        for (int k = 0; k < BK; k++) {
            float4 a0 = *(const float4*)&As[buf][k][tm * 8];
            float4 a1 = *(const float4*)&As[buf][k][tm * 8 + 4];
            float4 b0 = *(const float4*)&Bs[buf][k][tn * 8];
            float4 b1 = *(const float4*)&Bs[buf][k][tn * 8 + 4];
            float av[8] = {a0.x, a0.y, a0.z, a0.w, a1.x, a1.y, a1.z, a1.w};
            float bv[8] = {b0.x, b0.y, b0.z, b0.w, b1.x, b1.y, b1.z, b1.w};
            #pragma unroll
            for (int ii = 0; ii < 8; ii++)
                #pragma unroll
                for (int jj = 0; jj < 8; jj++)
                    acc[ii][jj] = fmaf(av[ii], bv[jj], acc[ii][jj]);
        }
        if (it + 1 < kIters) {
            #pragma unroll
            for (int i = 0; i < 4; i++) {
                As[buf ^ 1][la_k][la_m + 32 * i] = ra[i];
                Bs[buf ^ 1][lb_k + 2 * i][lb_n] = rb[i];
            }
        }
        __syncthreads();
        buf ^= 1;
    }
    int mrow = m0 + tm * 8;
    int bidx = mrow >> 11;
    int npt  = mrow & 2047;
    #pragma unroll
    for (int jj = 0; jj < 8; jj++) {
        int col = n0 + tn * 8 + jj;
        float gd = g[col], bd = bias[col];
        float h[8];
        #pragma unroll
        for (int ii = 0; ii < 8; ii++) {
            float z = fmaf(acc[ii][jj], gd, bd);
            h[ii] = z >= 0.f ? z : NEG_SLOPE * z;
        }
        size_t p = ((size_t)(bidx << 10) + col) * NPTS + npt;
        *(float4*)&out[p]     = make_float4(h[0], h[1], h[2], h[3]);
        *(float4*)&out[p + 4] = make_float4(h[4], h[5], h[6], h[7]);
    }
}

// ---------------- top-20: warp-local tournaments, barrier-free --------------
__global__ void __launch_bounds__(256) topk_kernel(const float* __restrict__ G,
                                                   const float* __restrict__ xx,
                                                   int* __restrict__ idxout) {
    __shared__ float swv[8 * KNN];
    __shared__ int   swi[8 * KNN];
    int row = blockIdx.x, b = row >> 11, tid = threadIdx.x;
    int lane = tid & 31, wid = tid >> 5;
    const float* Grow = G + (size_t)row * NPTS;
    const float* xxb = xx + (b << 11);
    float xxi = xx[row];
    float v[8];
    #pragma unroll
    for (int i = 0; i < 8; i++) {
        int j = tid + (i << 8);
        v[i] = 2.f * __ldg(&Grow[j]) - xxi - __ldg(&xxb[j]);
    }
    // phase 1: each warp extracts its local top-20 (no block barriers)
    #pragma unroll 1
    for (int r = 0; r < KNN; r++) {
        float bv = v[0]; int bs = 0;
        #pragma unroll
        for (int i = 1; i < 8; i++) if (v[i] > bv) { bv = v[i]; bs = i; }
        int bj = tid + (bs << 8);
        #pragma unroll
        for (int o = 16; o; o >>= 1) {
            float ov = __shfl_xor_sync(0xFFFFFFFFu, bv, o);
            int   oj = __shfl_xor_sync(0xFFFFFFFFu, bj, o);
            if (ov > bv || (ov == bv && oj < bj)) { bv = ov; bj = oj; }
        }
        if (lane == 0) { swv[wid * KNN + r] = bv; swi[wid * KNN + r] = bj; }
        if ((bj & 255) == tid) v[bj >> 8] = -FLT_MAX;
    }
    __syncthreads();
    // phase 2: warp 0 merges the 160 candidates
    if (wid == 0) {
        float mv[5];
        #pragma unroll
        for (int t = 0; t < 5; t++) mv[t] = swv[lane + (t << 5)];
        #pragma unroll 1
        for (int r = 0; r < KNN; r++) {
            float bv = mv[0]; int bc = lane;
            #pragma unroll
            for (int t = 1; t < 5; t++)
                if (mv[t] > bv) { bv = mv[t]; bc = lane + (t << 5); }
            #pragma unroll
            for (int o = 16; o; o >>= 1) {
                float ov = __shfl_xor_sync(0xFFFFFFFFu, bv, o);
                int   oc = __shfl_xor_sync(0xFFFFFFFFu, bc, o);
                if (ov > bv || (ov == bv && oc < bc)) { bv = ov; bc = oc; }
            }
            if ((bc & 31) == lane) {
                idxout[row * KNN + r] = (b << 11) + swi[bc];
                mv[bc >> 5] = -FLT_MAX;
            }
        }
    }
}

// ---------------- gather + max/min over neighbors + epilogue ----------------
__global__ void gathermax_kernel(const float* __restrict__ PC,
                                 const int* __restrict__ idx,
                                 const float* __restrict__ g,
                                 const float* __restrict__ bias,
                                 float* __restrict__ Xout, int cl) {
    int cout = 1 << cl;
    int i = blockIdx.x * 256 + threadIdx.x;
    int n = i >> cl, d = i & (cout - 1);
    int ld = cout << 1;
    const int* ip = idx + n * KNN;
    float mx = -FLT_MAX, mn = FLT_MAX;
    #pragma unroll
    for (int k = 0; k < KNN; k++) {
        float v = __ldg(&PC[(size_t)__ldg(&ip[k]) * ld + d]);
        mx = fmaxf(mx, v); mn = fminf(mn, v);
    }
    float Cc = PC[(size_t)n * ld + cout + d];
    float gd = g[d], bd = bias[d];
    float z = (gd >= 0.f ? mx : mn) + Cc;
    float h = fmaf(gd, z, bd);
    Xout[i] = h >= 0.f ? h : NEG_SLOPE * h;
}

// ---------------- combined weight: [W_a | W_b - W_a] ------------------------
__global__ void wcomb_kernel(const float* __restrict__ W, float* __restrict__ Wc,
                             int cin, int cout) {
    int i = blockIdx.x * 256 + threadIdx.x;
    int tot = cin * 2 * cout;
    if (i >= tot) return;
    int twoc = 2 * cout;
    int c = i / twoc, j = i - c * twoc;
    float v;
    if (j < cout) v = W[c * cout + j];
    else { int dd = j - cout; v = W[(cin + c) * cout + dd] - W[c * cout + dd]; }
    Wc[i] = v;
}

// ---------------- concat x1..x4 ---------------------------------------------
__global__ void cat_kernel(const float* __restrict__ a, const float* __restrict__ b,
                           const float* __restrict__ c, const float* __restrict__ d,
                           float* __restrict__ o) {
    int i = blockIdx.x * 256 + threadIdx.x;   // total NB*512
    int n = i >> 9, ch = i & 511;
    float v;
    if (ch < 64)        v = a[(size_t)n * 64  + ch];
    else if (ch < 128)  v = b[(size_t)n * 64  + ch - 64];
    else if (ch < 256)  v = c[(size_t)n * 128 + ch - 128];
    else                v = d[(size_t)n * 256 + ch - 256];
    o[i] = v;
}

// ---------------- host launch ------------------------------------------------
extern "C" void kernel_launch(void* const* d_in, const int* in_sizes, int n_in,
                              void* d_out, int out_size) {
    (void)in_sizes; (void)n_in; (void)out_size;
    const float* pts = (const float*)d_in[0];
    const float* W[5]; const float* gg[5]; const float* bb[5];
    for (int i = 0; i < 5; i++) {
        W[i]  = (const float*)d_in[1 + 3 * i];
        gg[i] = (const float*)d_in[2 + 3 * i];
        bb[i] = (const float*)d_in[3 + 3 * i];
    }
    float* out = (float*)d_out;

    float *X1, *X2, *X3, *X4, *PC, *G, *XX, *WC, *CAT; int* IDX;
    cudaGetSymbolAddress((void**)&X1,  g_X1);
    cudaGetSymbolAddress((void**)&X2,  g_X2);
    cudaGetSymbolAddress((void**)&X3,  g_X3);
    cudaGetSymbolAddress((void**)&X4,  g_X4);
    cudaGetSymbolAddress((void**)&PC,  g_PC);
    cudaGetSymbolAddress((void**)&G,   g_G);
    cudaGetSymbolAddress((void**)&XX,  g_xx);
    cudaGetSymbolAddress((void**)&WC,  g_Wcomb);
    cudaGetSymbolAddress((void**)&CAT, g_cat);
    cudaGetSymbolAddress((void**)&IDX, g_idx);

    struct L { const float* Xin; int cin, cout, cl; float* Xout; };
    L layers[4] = {
        { pts, 3,   64,  6, X1 },
        { X1,  64,  64,  6, X2 },
        { X2,  64,  128, 7, X3 },
        { X3,  128, 256, 8, X4 },
    };
    for (int li = 0; li < 4; li++) {
        const L& l = layers[li];
        xx_kernel<<<NB / 8, 256>>>(l.Xin, XX, l.cin);
        gram_gemm<<<dim3(NPTS / BN, NPTS / BM, BATCH), 256>>>(l.Xin, G, l.cin);
        topk_kernel<<<NB, 256>>>(G, XX, IDX);
        int tot = l.cin * 2 * l.cout;
        wcomb_kernel<<<(tot + 255) / 256, 256>>>(W[li], WC, l.cin, l.cout);
        gemm_nn<<<dim3((2 * l.cout) / BN, NB / BM), 256>>>(l.Xin, WC, PC, 2 * l.cout, l.cin);
        gathermax_kernel<<<(NB * l.cout) / 256, 256>>>(PC, IDX, gg[li], bb[li], l.Xout, l.cl);
    }
    cat_kernel<<<(NB * 512) / 256, 256>>>(X1, X2, X3, X4, CAT);
    gemm_w5<<<dim3(1024 / BN, NB / BM), 256>>>(CAT, W[4], gg[4], bb[4], out, 1024, 512);
}

// round 10
// speedup vs baseline: 1.5647x; 1.3102x over previous
#include <cuda_runtime.h>
#include <cuda_bf16.h>
#include <float.h>
#include <stdint.h>

#define NB    16384
#define NPTS  2048
#define BATCH 8
#define KNN   20
#define NEG_SLOPE 0.2f

#define BM 128
#define BN 128
#define BK 8

// ---------------- scratch (device globals) ----------------------------------
__device__ float g_X1[NB * 64];
__device__ float g_X2[NB * 64];
__device__ float g_X3[NB * 128];
__device__ float g_X4[NB * 256];
__device__ float g_PC[NB * 512];
__device__ float g_G[(size_t)BATCH * NPTS * NPTS];   // holds negd
__device__ float g_xx[NB];
__device__ int   g_idx[NB * KNN];
__device__ float g_Wcomb[128 * 512];
__device__ __nv_bfloat16 g_XexpA[(size_t)NB * 384];
__device__ __nv_bfloat16 g_XexpB[(size_t)NB * 384];
__device__ __nv_bfloat16 g_CATexp[(size_t)NB * 1536];
__device__ __nv_bfloat16 g_W5exp[(size_t)1024 * 1536];

// ======================= warp-MMA helpers (plain PTX, sm_80+) ================
__device__ __forceinline__ uint32_t smem_u32(const void* p) {
    uint32_t a;
    asm("{ .reg .u64 t; cvta.to.shared.u64 t, %1; cvt.u32.u64 %0, t; }"
        : "=r"(a) : "l"(p));
    return a;
}

#define SWZ(o) ((o) ^ (((o) >> 3) & 0x70))

#define LDSM4(r, a) \
    asm volatile("ldmatrix.sync.aligned.m8n8.x4.shared.b16 {%0,%1,%2,%3}, [%4];" \
        : "=r"((r)[0]), "=r"((r)[1]), "=r"((r)[2]), "=r"((r)[3]) : "r"(a))

#define MMA16816(d, a, b0, b1) \
    asm volatile("mma.sync.aligned.m16n8k16.row.col.f32.bf16.bf16.f32 " \
        "{%0,%1,%2,%3},{%4,%5,%6,%7},{%8,%9},{%0,%1,%2,%3};" \
        : "+f"((d)[0]), "+f"((d)[1]), "+f"((d)[2]), "+f"((d)[3]) \
        : "r"((a)[0]), "r"((a)[1]), "r"((a)[2]), "r"((a)[3]), "r"(b0), "r"(b1))

#define STAGE_B 16384               // 128 rows x 128 bytes
#define HM_SMEM (4 * STAGE_B + 128) // 2 stages x 2 operands + align slack

// mainloop: acc += A(128 x 64*kc) * B(128 x 64*kc)^T, both row-major bf16
__device__ __forceinline__ void hmma_loop(char* sm, const char* Ag, const char* Bg,
                                          size_t strA, size_t strB, int kchunks,
                                          int tid, float acc[2][8][4]) {
    char* sA = sm;
    char* sB = sm + 2 * STAGE_B;
    int lane = tid & 31, wid = tid >> 5;
    int wm = wid & 3, wn = wid >> 2;
    int r = tid >> 3, cbyte = (tid & 7) * 16;
    // preload stage 0
    #pragma unroll
    for (int i = 0; i < 4; i++) {
        int row = r + 32 * i;
        *(uint4*)(sA + SWZ(row * 128 + cbyte)) = *(const uint4*)(Ag + (size_t)row * strA + cbyte);
        *(uint4*)(sB + SWZ(row * 128 + cbyte)) = *(const uint4*)(Bg + (size_t)row * strB + cbyte);
    }
    __syncthreads();
    uint32_t sA32 = smem_u32(sA), sB32 = smem_u32(sB);
    int buf = 0;
    for (int c = 0; c < kchunks; c++) {
        uint4 pa[4], pb[4];
        if (c + 1 < kchunks) {
            const char* An = Ag + (size_t)(c + 1) * 128;
            const char* Bn = Bg + (size_t)(c + 1) * 128;
            #pragma unroll
            for (int i = 0; i < 4; i++) {
                int row = r + 32 * i;
                pa[i] = *(const uint4*)(An + (size_t)row * strA + cbyte);
                pb[i] = *(const uint4*)(Bn + (size_t)row * strB + cbyte);
            }
        }
        uint32_t aB = sA32 + buf * STAGE_B, bB = sB32 + buf * STAGE_B;
        #pragma unroll
        for (int ks = 0; ks < 4; ks++) {
            uint32_t a[2][4], b[4][4];
            #pragma unroll
            for (int mi = 0; mi < 2; mi++) {
                int row = wm * 32 + mi * 16 + (lane & 15);
                int off = row * 128 + ks * 32 + ((lane >> 4) << 4);
                LDSM4(a[mi], aB + SWZ(off));
            }
            #pragma unroll
            for (int np = 0; np < 4; np++) {
                int row = wn * 64 + np * 16 + ((lane >> 4) << 3) + (lane & 7);
                int off = row * 128 + ks * 32 + (((lane >> 3) & 1) << 4);
                LDSM4(b[np], bB + SWZ(off));
            }
            #pragma unroll
            for (int mi = 0; mi < 2; mi++)
                #pragma unroll
                for (int nj = 0; nj < 8; nj++)
                    MMA16816(acc[mi][nj], a[mi], b[nj >> 1][(nj & 1) * 2], b[nj >> 1][(nj & 1) * 2 + 1]);
        }
        if (c + 1 < kchunks) {
            char* dA = sA + (buf ^ 1) * STAGE_B;
            char* dB = sB + (buf ^ 1) * STAGE_B;
            #pragma unroll
            for (int i = 0; i < 4; i++) {
                int row = r + 32 * i;
                *(uint4*)(dA + SWZ(row * 128 + cbyte)) = pa[i];
                *(uint4*)(dB + SWZ(row * 128 + cbyte)) = pb[i];
            }
            __syncthreads();
            buf ^= 1;
        }
    }
}

// --------- Gram (triangular blocks): negd = 2*X@X^T - xx_m - xx_n ------------
__global__ void __launch_bounds__(256) gram_hmma(const __nv_bfloat16* __restrict__ Ae,
                                                 const __nv_bfloat16* __restrict__ Be,
                                                 const float* __restrict__ xx,
                                                 float* __restrict__ negd, int Kexp) {
    extern __shared__ char dsm[];
    uint32_t sb = smem_u32(dsm);
    char* sm = dsm + (((sb + 127) & ~127u) - sb);
    int tid = threadIdx.x, lane = tid & 31, wid = tid >> 5;
    int wm = wid & 3, wn = wid >> 2;
    int b = blockIdx.z;
    // triangular decode: block -> (ti, tj), tj >= ti, 16x16 tile grid
    int rem = blockIdx.x, ti = 0;
    while (rem >= 16 - ti) { rem -= 16 - ti; ti++; }
    int tj = ti + rem;
    int m0 = ti * 128, n0 = tj * 128;

    float acc[2][8][4] = {};
    size_t str = (size_t)Kexp * 2;
    hmma_loop(sm, (const char*)(Ae + (size_t)(b * NPTS + m0) * Kexp),
                  (const char*)(Be + (size_t)(b * NPTS + n0) * Kexp),
              str, str, Kexp >> 6, tid, acc);

    const float* xxb = xx + b * NPTS;
    float* nd = negd + ((size_t)b << 22);
    #pragma unroll
    for (int mi = 0; mi < 2; mi++) {
        int rowa = m0 + wm * 32 + mi * 16 + (lane >> 2);
        float xm0 = __ldg(&xxb[rowa]), xm1 = __ldg(&xxb[rowa + 8]);
        #pragma unroll
        for (int nj = 0; nj < 8; nj++) {
            int col = n0 + wn * 64 + nj * 8 + (lane & 3) * 2;
            float xn0 = __ldg(&xxb[col]), xn1 = __ldg(&xxb[col + 1]);
            float v00 = 2.f * acc[mi][nj][0] - xm0 - xn0;
            float v01 = 2.f * acc[mi][nj][1] - xm0 - xn1;
            float v10 = 2.f * acc[mi][nj][2] - xm1 - xn0;
            float v11 = 2.f * acc[mi][nj][3] - xm1 - xn1;
            *(float2*)&nd[(size_t)rowa * NPTS + col]       = make_float2(v00, v01);
            *(float2*)&nd[(size_t)(rowa + 8) * NPTS + col] = make_float2(v10, v11);
            if (ti != tj) {   // mirror (G symmetric)
                nd[(size_t)col * NPTS + rowa]           = v00;
                nd[(size_t)(col + 1) * NPTS + rowa]     = v01;
                nd[(size_t)col * NPTS + rowa + 8]       = v10;
                nd[(size_t)(col + 1) * NPTS + rowa + 8] = v11;
            }
        }
    }
}

// --------- W5: out = lrelu(cat@W5 * g + b), transposed store -----------------
__global__ void __launch_bounds__(256) w5_hmma(const __nv_bfloat16* __restrict__ Ae,
                                               const __nv_bfloat16* __restrict__ Be,
                                               const float* __restrict__ g,
                                               const float* __restrict__ bias,
                                               float* __restrict__ out) {
    extern __shared__ char dsm[];
    uint32_t sb = smem_u32(dsm);
    char* sm = dsm + (((sb + 127) & ~127u) - sb);
    int tid = threadIdx.x, lane = tid & 31, wid = tid >> 5;
    int wm = wid & 3, wn = wid >> 2;
    int m0 = blockIdx.y * 128, n0 = blockIdx.x * 128;

    float acc[2][8][4] = {};
    hmma_loop(sm, (const char*)(Ae + (size_t)m0 * 1536),
                  (const char*)(Be + (size_t)n0 * 1536),
              3072, 3072, 24, tid, acc);

    #pragma unroll
    for (int mi = 0; mi < 2; mi++) {
        int m = m0 + wm * 32 + mi * 16 + (lane >> 2);
        #pragma unroll
        for (int half = 0; half < 2; half++) {
            int mr = m + half * 8;
            int bidx = mr >> 11, npt = mr & 2047;
            size_t obase = ((size_t)bidx << 10) * NPTS + npt;
            #pragma unroll
            for (int nj = 0; nj < 8; nj++) {
                int col = n0 + wn * 64 + nj * 8 + (lane & 3) * 2;
                float g0 = __ldg(&g[col]), g1 = __ldg(&g[col + 1]);
                float b0 = __ldg(&bias[col]), b1 = __ldg(&bias[col + 1]);
                float z0 = fmaf(acc[mi][nj][half * 2],     g0, b0);
                float z1 = fmaf(acc[mi][nj][half * 2 + 1], g1, b1);
                out[obase + (size_t)col * NPTS]       = z0 >= 0.f ? z0 : NEG_SLOPE * z0;
                out[obase + (size_t)(col + 1) * NPTS] = z1 >= 0.f ? z1 : NEG_SLOPE * z1;
            }
        }
    }
}

// ---------------- bf16x3 expansion kernels ----------------------------------
__global__ void expand_gram(const float* __restrict__ X, __nv_bfloat16* __restrict__ Ae,
                            __nv_bfloat16* __restrict__ Be, int K, int Kexp) {
    long long i = (long long)blockIdx.x * 256 + threadIdx.x;
    if (i >= (long long)NB * Kexp) return;
    int m = (int)(i / Kexp), k = (int)(i - (long long)m * Kexp);
    int t = (k < K) ? 0 : (k < 2 * K) ? 1 : (k < 3 * K) ? 2 : 3;
    __nv_bfloat16 av, bv;
    if (t == 3) { av = __float2bfloat16(0.f); bv = av; }
    else {
        float v = X[(size_t)m * K + (k - t * K)];
        __nv_bfloat16 hi = __float2bfloat16(v);
        __nv_bfloat16 lo = __float2bfloat16(v - __bfloat162float(hi));
        av = (t == 2) ? lo : hi;
        bv = (t == 1) ? lo : hi;
    }
    Ae[i] = av; Be[i] = bv;
}

__global__ void expand_cat(const float* __restrict__ X1, const float* __restrict__ X2,
                           const float* __restrict__ X3, const float* __restrict__ X4,
                           __nv_bfloat16* __restrict__ Ae) {
    long long i = (long long)blockIdx.x * 256 + threadIdx.x;   // NB*1536
    int m = (int)(i / 1536);
    int k = (int)(i - (long long)m * 1536);
    int t = k >> 9, k0 = k & 511;
    float v;
    if (k0 < 64)       v = X1[(size_t)m * 64 + k0];
    else if (k0 < 128) v = X2[(size_t)m * 64 + k0 - 64];
    else if (k0 < 256) v = X3[(size_t)m * 128 + k0 - 128];
    else               v = X4[(size_t)m * 256 + k0 - 256];
    __nv_bfloat16 hi = __float2bfloat16(v);
    Ae[i] = (t == 2) ? __float2bfloat16(v - __bfloat162float(hi)) : hi;
}

__global__ void expand_w5(const float* __restrict__ W, __nv_bfloat16* __restrict__ Be) {
    long long i = (long long)blockIdx.x * 256 + threadIdx.x;   // 1024*1536
    int n = (int)(i / 1536);
    int k = (int)(i - (long long)n * 1536);
    int t = k >> 9, k0 = k & 511;
    float v = W[(size_t)k0 * 1024 + n];
    __nv_bfloat16 hi = __float2bfloat16(v);
    Be[i] = (t == 1) ? __float2bfloat16(v - __bfloat162float(hi)) : hi;
}

// ---------------- squared norms ----------------------------------------------
__global__ void xx_kernel(const float* __restrict__ X, float* __restrict__ xx, int C) {
    int gw = (blockIdx.x * blockDim.x + threadIdx.x) >> 5;
    int lane = threadIdx.x & 31;
    if (gw >= NB) return;
    const float* row = X + (size_t)gw * C;
    float s = 0.f;
    for (int c = lane; c < C; c += 32) { float v = row[c]; s += v * v; }
    #pragma unroll
    for (int o = 16; o > 0; o >>= 1) s += __shfl_xor_sync(0xFFFFFFFFu, s, o);
    if (lane == 0) xx[gw] = s;
}

// ---------------- generic SIMT C = A @ B (for PC) ----------------------------
__global__ void __launch_bounds__(256, 2) gemm_nn(const float* __restrict__ A,
                                                  const float* __restrict__ B,
                                                  float* __restrict__ Cout,
                                                  int N, int Kdim) {
    __shared__ float As[2][BK][BM + 4];
    __shared__ float Bs[2][BK][BN + 4];
    int tid = threadIdx.x;
    int m0 = blockIdx.y * BM, n0 = blockIdx.x * BN;
    int tm = tid >> 4, tn = tid & 15;
    int la_m = tid >> 3, la_k = tid & 7;
    int lb_k = tid >> 7, lb_n = tid & 127;
    float acc[8][8] = {};
    float ra[4], rb[4];
    int kIters = (Kdim + BK - 1) / BK;
    #pragma unroll
    for (int i = 0; i < 4; i++) {
        int m = la_m + 32 * i;
        ra[i] = (la_k < Kdim) ? A[(size_t)(m0 + m) * Kdim + la_k] : 0.f;
        int kb = lb_k + 2 * i;
        rb[i] = (kb < Kdim) ? B[(size_t)kb * N + n0 + lb_n] : 0.f;
    }
    #pragma unroll
    for (int i = 0; i < 4; i++) {
        As[0][la_k][la_m + 32 * i] = ra[i];
        Bs[0][lb_k + 2 * i][lb_n] = rb[i];
    }
    __syncthreads();
    int buf = 0;
    for (int it = 0; it < kIters; ++it) {
        if (it + 1 < kIters) {
            int k0n = (it + 1) * BK;
            #pragma unroll
            for (int i = 0; i < 4; i++) {
                int m = la_m + 32 * i;
                int ka = k0n + la_k;
                ra[i] = (ka < Kdim) ? A[(size_t)(m0 + m) * Kdim + ka] : 0.f;
                int kb = k0n + lb_k + 2 * i;
                rb[i] = (kb < Kdim) ? B[(size_t)kb * N + n0 + lb_n] : 0.f;
            }
        }
        #pragma unroll
        for (int k = 0; k < BK; k++) {
            float4 A0v = *(const float4*)&As[buf][k][tm * 8];
            float4 A1v = *(const float4*)&As[buf][k][tm * 8 + 4];
            float4 B0v = *(const float4*)&Bs[buf][k][tn * 8];
            float4 B1v = *(const float4*)&Bs[buf][k][tn * 8 + 4];
            float av[8] = {A0v.x, A0v.y, A0v.z, A0v.w, A1v.x, A1v.y, A1v.z, A1v.w};
            float bv[8] = {B0v.x, B0v.y, B0v.z, B0v.w, B1v.x, B1v.y, B1v.z, B1v.w};
            #pragma unroll
            for (int ii = 0; ii < 8; ii++)
                #pragma unroll
                for (int jj = 0; jj < 8; jj++)
                    acc[ii][jj] = fmaf(av[ii], bv[jj], acc[ii][jj]);
        }
        if (it + 1 < kIters) {
            #pragma unroll
            for (int i = 0; i < 4; i++) {
                As[buf ^ 1][la_k][la_m + 32 * i] = ra[i];
                Bs[buf ^ 1][lb_k + 2 * i][lb_n] = rb[i];
            }
        }
        __syncthreads();
        buf ^= 1;
    }
    #pragma unroll
    for (int ii = 0; ii < 8; ii++) {
        size_t p = (size_t)(m0 + tm * 8 + ii) * N + n0 + tn * 8;
        *(float4*)&Cout[p]     = make_float4(acc[ii][0], acc[ii][1], acc[ii][2], acc[ii][3]);
        *(float4*)&Cout[p + 4] = make_float4(acc[ii][4], acc[ii][5], acc[ii][6], acc[ii][7]);
    }
}

// ---------------- top-20 (reads precomputed negd rows) -----------------------
__global__ void __launch_bounds__(256) topk_kernel(const float* __restrict__ negd,
                                                   int* __restrict__ idxout) {
    __shared__ float swv[8 * KNN];
    __shared__ int   swi[8 * KNN];
    int row = blockIdx.x, b = row >> 11, tid = threadIdx.x;
    int lane = tid & 31, wid = tid >> 5;
    const float* Grow = negd + (size_t)row * NPTS;
    float v[8];
    #pragma unroll
    for (int i = 0; i < 8; i++) v[i] = __ldg(&Grow[tid + (i << 8)]);
    #pragma unroll 1
    for (int r = 0; r < KNN; r++) {
        float bv = v[0]; int bs = 0;
        #pragma unroll
        for (int i = 1; i < 8; i++) if (v[i] > bv) { bv = v[i]; bs = i; }
        int bj = tid + (bs << 8);
        #pragma unroll
        for (int o = 16; o; o >>= 1) {
            float ov = __shfl_xor_sync(0xFFFFFFFFu, bv, o);
            int   oj = __shfl_xor_sync(0xFFFFFFFFu, bj, o);
            if (ov > bv || (ov == bv && oj < bj)) { bv = ov; bj = oj; }
        }
        if (lane == 0) { swv[wid * KNN + r] = bv; swi[wid * KNN + r] = bj; }
        if ((bj & 255) == tid) v[bj >> 8] = -FLT_MAX;
    }
    __syncthreads();
    if (wid == 0) {
        float mv[5];
        #pragma unroll
        for (int t = 0; t < 5; t++) mv[t] = swv[lane + (t << 5)];
        #pragma unroll 1
        for (int r = 0; r < KNN; r++) {
            float bv = mv[0]; int bc = lane;
            #pragma unroll
            for (int t = 1; t < 5; t++)
                if (mv[t] > bv) { bv = mv[t]; bc = lane + (t << 5); }
            #pragma unroll
            for (int o = 16; o; o >>= 1) {
                float ov = __shfl_xor_sync(0xFFFFFFFFu, bv, o);
                int   oc = __shfl_xor_sync(0xFFFFFFFFu, bc, o);
                if (ov > bv || (ov == bv && oc < bc)) { bv = ov; bc = oc; }
            }
            if ((bc & 31) == lane) {
                idxout[row * KNN + r] = (b << 11) + swi[bc];
                mv[bc >> 5] = -FLT_MAX;
            }
        }
    }
}

// ---------------- gather + max/min + epilogue --------------------------------
__global__ void gathermax_kernel(const float* __restrict__ PC,
                                 const int* __restrict__ idx,
                                 const float* __restrict__ g,
                                 const float* __restrict__ bias,
                                 float* __restrict__ Xout, int cl) {
    int cout = 1 << cl;
    int i = blockIdx.x * 256 + threadIdx.x;
    int n = i >> cl, d = i & (cout - 1);
    int ld = cout << 1;
    const int* ip = idx + n * KNN;
    float mx = -FLT_MAX, mn = FLT_MAX;
    #pragma unroll
    for (int k = 0; k < KNN; k++) {
        float v = __ldg(&PC[(size_t)__ldg(&ip[k]) * ld + d]);
        mx = fmaxf(mx, v); mn = fminf(mn, v);
    }
    float Cc = PC[(size_t)n * ld + cout + d];
    float gd = g[d], bd = bias[d];
    float z = (gd >= 0.f ? mx : mn) + Cc;
    float h = fmaf(gd, z, bd);
    Xout[i] = h >= 0.f ? h : NEG_SLOPE * h;
}

// ---------------- combined weight: [W_a | W_b - W_a] -------------------------
__global__ void wcomb_kernel(const float* __restrict__ W, float* __restrict__ Wc,
                             int cin, int cout) {
    int i = blockIdx.x * 256 + threadIdx.x;
    int tot = cin * 2 * cout;
    if (i >= tot) return;
    int twoc = 2 * cout;
    int c = i / twoc, j = i - c * twoc;
    float v;
    if (j < cout) v = W[c * cout + j];
    else { int dd = j - cout; v = W[(cin + c) * cout + dd] - W[c * cout + dd]; }
    Wc[i] = v;
}

// ---------------- host launch -------------------------------------------------
extern "C" void kernel_launch(void* const* d_in, const int* in_sizes, int n_in,
                              void* d_out, int out_size) {
    (void)in_sizes; (void)n_in; (void)out_size;
    const float* pts = (const float*)d_in[0];
    const float* W[5]; const float* gg[5]; const float* bb[5];
    for (int i = 0; i < 5; i++) {
        W[i]  = (const float*)d_in[1 + 3 * i];
        gg[i] = (const float*)d_in[2 + 3 * i];
        bb[i] = (const float*)d_in[3 + 3 * i];
    }
    float* out = (float*)d_out;

    float *X1, *X2, *X3, *X4, *PC, *G, *XX, *WC; int* IDX;
    __nv_bfloat16 *XA, *XB, *CE, *WE;
    cudaGetSymbolAddress((void**)&X1, g_X1);
    cudaGetSymbolAddress((void**)&X2, g_X2);
    cudaGetSymbolAddress((void**)&X3, g_X3);
    cudaGetSymbolAddress((void**)&X4, g_X4);
    cudaGetSymbolAddress((void**)&PC, g_PC);
    cudaGetSymbolAddress((void**)&G,  g_G);
    cudaGetSymbolAddress((void**)&XX, g_xx);
    cudaGetSymbolAddress((void**)&WC, g_Wcomb);
    cudaGetSymbolAddress((void**)&IDX, g_idx);
    cudaGetSymbolAddress((void**)&XA, g_XexpA);
    cudaGetSymbolAddress((void**)&XB, g_XexpB);
    cudaGetSymbolAddress((void**)&CE, g_CATexp);
    cudaGetSymbolAddress((void**)&WE, g_W5exp);

    cudaFuncSetAttribute(gram_hmma, cudaFuncAttributeMaxDynamicSharedMemorySize, HM_SMEM);
    cudaFuncSetAttribute(w5_hmma,   cudaFuncAttributeMaxDynamicSharedMemorySize, HM_SMEM);

    struct L { const float* Xin; int cin, cout, cl, kexp; float* Xout; };
    L layers[4] = {
        { pts, 3,   64,  6, 64,  X1 },
        { X1,  64,  64,  6, 192, X2 },
        { X2,  64,  128, 7, 192, X3 },
        { X3,  128, 256, 8, 384, X4 },
    };
    for (int li = 0; li < 4; li++) {
        const L& l = layers[li];
        xx_kernel<<<NB / 8, 256>>>(l.Xin, XX, l.cin);
        long long etot = (long long)NB * l.kexp;
        expand_gram<<<(unsigned)((etot + 255) / 256), 256>>>(l.Xin, XA, XB, l.cin, l.kexp);
        gram_hmma<<<dim3(136, 1, BATCH), 256, HM_SMEM>>>(XA, XB, XX, G, l.kexp);
        topk_kernel<<<NB, 256>>>(G, IDX);
        int tot = l.cin * 2 * l.cout;
        wcomb_kernel<<<(tot + 255) / 256, 256>>>(W[li], WC, l.cin, l.cout);
        gemm_nn<<<dim3((2 * l.cout) / BN, NB / BM), 256>>>(l.Xin, WC, PC, 2 * l.cout, l.cin);
        gathermax_kernel<<<(NB * l.cout) / 256, 256>>>(PC, IDX, gg[li], bb[li], l.Xout, l.cl);
    }
    expand_cat<<<(unsigned)(((long long)NB * 1536 + 255) / 256), 256>>>(X1, X2, X3, X4, CE);
    expand_w5<<<(1024 * 1536) / 256, 256>>>(W[4], WE);
    w5_hmma<<<dim3(1024 / 128, NB / 128), 256, HM_SMEM>>>(CE, WE, gg[4], bb[4], out);
}

// round 11
// speedup vs baseline: 2.6614x; 1.7009x over previous
#include <cuda_runtime.h>
#include <cuda_bf16.h>
#include <float.h>
#include <stdint.h>

#define NB    16384
#define NPTS  2048
#define BATCH 8
#define KNN   20
#define NEG_SLOPE 0.2f

#define BM 128
#define BN 128
#define BK 8

// ---------------- scratch (device globals) ----------------------------------
__device__ float g_X1[NB * 64];
__device__ float g_X2[NB * 64];
__device__ float g_X3[NB * 128];
__device__ float g_X4[NB * 256];
__device__ float g_PC[NB * 512];
__device__ float g_G[(size_t)BATCH * NPTS * NPTS];   // holds negd
__device__ float g_xx[NB];
__device__ int   g_idx[NB * KNN];
__device__ float g_Wcomb[128 * 512];
__device__ __nv_bfloat16 g_XexpA[(size_t)NB * 384];
__device__ __nv_bfloat16 g_XexpB[(size_t)NB * 384];
__device__ __nv_bfloat16 g_CATexp[(size_t)NB * 1536];
__device__ __nv_bfloat16 g_W5exp[(size_t)1024 * 1536];

// ======================= warp-MMA helpers (plain PTX, sm_80+) ================
__device__ __forceinline__ uint32_t smem_u32(const void* p) {
    uint32_t a;
    asm("{ .reg .u64 t; cvta.to.shared.u64 t, %1; cvt.u32.u64 %0, t; }"
        : "=r"(a) : "l"(p));
    return a;
}

#define SWZ(o) ((o) ^ (((o) >> 3) & 0x70))

#define LDSM4(r, a) \
    asm volatile("ldmatrix.sync.aligned.m8n8.x4.shared.b16 {%0,%1,%2,%3}, [%4];" \
        : "=r"((r)[0]), "=r"((r)[1]), "=r"((r)[2]), "=r"((r)[3]) : "r"(a))

#define MMA16816(d, a, b0, b1) \
    asm volatile("mma.sync.aligned.m16n8k16.row.col.f32.bf16.bf16.f32 " \
        "{%0,%1,%2,%3},{%4,%5,%6,%7},{%8,%9},{%0,%1,%2,%3};" \
        : "+f"((d)[0]), "+f"((d)[1]), "+f"((d)[2]), "+f"((d)[3]) \
        : "r"((a)[0]), "r"((a)[1]), "r"((a)[2]), "r"((a)[3]), "r"(b0), "r"(b1))

#define STAGE_B 16384                      // 128 rows x 128 bytes
#define W5_SMEM (4 * STAGE_B + 128)        // 2 stages x 2 operands
#define TILE_PITCH 133
#define GR_SMEM (128 * TILE_PITCH * 4 + 256)  // transpose tile dominates (68KB+)

// mainloop: acc += A(128 x 64*kc) * B(128 x 64*kc)^T, both row-major bf16
__device__ __forceinline__ void hmma_loop(char* sm, const char* Ag, const char* Bg,
                                          size_t strA, size_t strB, int kchunks,
                                          int tid, float acc[2][8][4]) {
    char* sA = sm;
    char* sB = sm + 2 * STAGE_B;
    int lane = tid & 31, wid = tid >> 5;
    int wm = wid & 3, wn = wid >> 2;
    int r = tid >> 3, cbyte = (tid & 7) * 16;
    #pragma unroll
    for (int i = 0; i < 4; i++) {
        int row = r + 32 * i;
        *(uint4*)(sA + SWZ(row * 128 + cbyte)) = *(const uint4*)(Ag + (size_t)row * strA + cbyte);
        *(uint4*)(sB + SWZ(row * 128 + cbyte)) = *(const uint4*)(Bg + (size_t)row * strB + cbyte);
    }
    __syncthreads();
    uint32_t sA32 = smem_u32(sA), sB32 = smem_u32(sB);
    int buf = 0;
    for (int c = 0; c < kchunks; c++) {
        uint4 pa[4], pb[4];
        if (c + 1 < kchunks) {
            const char* An = Ag + (size_t)(c + 1) * 128;
            const char* Bn = Bg + (size_t)(c + 1) * 128;
            #pragma unroll
            for (int i = 0; i < 4; i++) {
                int row = r + 32 * i;
                pa[i] = *(const uint4*)(An + (size_t)row * strA + cbyte);
                pb[i] = *(const uint4*)(Bn + (size_t)row * strB + cbyte);
            }
        }
        uint32_t aB = sA32 + buf * STAGE_B, bB = sB32 + buf * STAGE_B;
        #pragma unroll
        for (int ks = 0; ks < 4; ks++) {
            uint32_t a[2][4], b[4][4];
            #pragma unroll
            for (int mi = 0; mi < 2; mi++) {
                int row = wm * 32 + mi * 16 + (lane & 15);
                int off = row * 128 + ks * 32 + ((lane >> 4) << 4);
                LDSM4(a[mi], aB + SWZ(off));
            }
            #pragma unroll
            for (int np = 0; np < 4; np++) {
                int row = wn * 64 + np * 16 + ((lane >> 4) << 3) + (lane & 7);
                int off = row * 128 + ks * 32 + (((lane >> 3) & 1) << 4);
                LDSM4(b[np], bB + SWZ(off));
            }
            #pragma unroll
            for (int mi = 0; mi < 2; mi++)
                #pragma unroll
                for (int nj = 0; nj < 8; nj++)
                    MMA16816(acc[mi][nj], a[mi], b[nj >> 1][(nj & 1) * 2], b[nj >> 1][(nj & 1) * 2 + 1]);
        }
        if (c + 1 < kchunks) {
            char* dA = sA + (buf ^ 1) * STAGE_B;
            char* dB = sB + (buf ^ 1) * STAGE_B;
            #pragma unroll
            for (int i = 0; i < 4; i++) {
                int row = r + 32 * i;
                *(uint4*)(dA + SWZ(row * 128 + cbyte)) = pa[i];
                *(uint4*)(dB + SWZ(row * 128 + cbyte)) = pb[i];
            }
            __syncthreads();
            buf ^= 1;
        }
    }
}

// --------- Gram (triangular blocks): negd = 2*X@X^T - xx_m - xx_n ------------
__global__ void __launch_bounds__(256) gram_hmma(const __nv_bfloat16* __restrict__ Ae,
                                                 const __nv_bfloat16* __restrict__ Be,
                                                 const float* __restrict__ xx,
                                                 float* __restrict__ negd, int Kexp) {
    extern __shared__ char dsm[];
    uint32_t sb = smem_u32(dsm);
    char* sm = dsm + (((sb + 127) & ~127u) - sb);
    int tid = threadIdx.x, lane = tid & 31, wid = tid >> 5;
    int wm = wid & 3, wn = wid >> 2;
    int b = blockIdx.z;
    // triangular decode: block -> (ti, tj), tj >= ti, 16x16 tile grid
    int rem = blockIdx.x, ti = 0;
    while (rem >= 16 - ti) { rem -= 16 - ti; ti++; }
    int tj = ti + rem;
    int m0 = ti * 128, n0 = tj * 128;

    float acc[2][8][4] = {};
    size_t str = (size_t)Kexp * 2;
    hmma_loop(sm, (const char*)(Ae + (size_t)(b * NPTS + m0) * Kexp),
                  (const char*)(Be + (size_t)(b * NPTS + n0) * Kexp),
              str, str, Kexp >> 6, tid, acc);

    const float* xxb = xx + b * NPTS;
    float* nd = negd + ((size_t)b << 22);
    float (*tile)[TILE_PITCH] = (float(*)[TILE_PITCH])sm;

    if (ti != tj) __syncthreads();    // uniform: mainloop smem reuse for tile

    #pragma unroll
    for (int mi = 0; mi < 2; mi++) {
        int lm0 = wm * 32 + mi * 16 + (lane >> 2);
        int rowa = m0 + lm0;
        float xm0 = __ldg(&xxb[rowa]), xm1 = __ldg(&xxb[rowa + 8]);
        #pragma unroll
        for (int nj = 0; nj < 8; nj++) {
            int ln = wn * 64 + nj * 8 + (lane & 3) * 2;
            int col = n0 + ln;
            float xn0 = __ldg(&xxb[col]), xn1 = __ldg(&xxb[col + 1]);
            float v00 = 2.f * acc[mi][nj][0] - xm0 - xn0;
            float v01 = 2.f * acc[mi][nj][1] - xm0 - xn1;
            float v10 = 2.f * acc[mi][nj][2] - xm1 - xn0;
            float v11 = 2.f * acc[mi][nj][3] - xm1 - xn1;
            *(float2*)&nd[(size_t)rowa * NPTS + col]       = make_float2(v00, v01);
            *(float2*)&nd[(size_t)(rowa + 8) * NPTS + col] = make_float2(v10, v11);
            if (ti != tj) {
                tile[lm0][ln]         = v00;
                tile[lm0][ln + 1]     = v01;
                tile[lm0 + 8][ln]     = v10;
                tile[lm0 + 8][ln + 1] = v11;
            }
        }
    }
    if (ti != tj) {      // coalesced mirror store via smem transpose
        __syncthreads();
        int nn = tid >> 1;
        int mmBase = (tid & 1) * 64;
        size_t gbase = (size_t)(n0 + nn) * NPTS + m0 + mmBase;
        #pragma unroll
        for (int k4 = 0; k4 < 16; k4++) {
            int mm = mmBase + k4 * 4;
            float4 w = make_float4(tile[mm][nn], tile[mm + 1][nn],
                                   tile[mm + 2][nn], tile[mm + 3][nn]);
            *(float4*)&nd[gbase + k4 * 4] = w;
        }
    }
}

// --------- W5: out = lrelu(cat@W5 * g + b), transposed store -----------------
__global__ void __launch_bounds__(256) w5_hmma(const __nv_bfloat16* __restrict__ Ae,
                                               const __nv_bfloat16* __restrict__ Be,
                                               const float* __restrict__ g,
                                               const float* __restrict__ bias,
                                               float* __restrict__ out) {
    extern __shared__ char dsm[];
    uint32_t sb = smem_u32(dsm);
    char* sm = dsm + (((sb + 127) & ~127u) - sb);
    int tid = threadIdx.x, lane = tid & 31, wid = tid >> 5;
    int wm = wid & 3, wn = wid >> 2;
    int m0 = blockIdx.y * 128, n0 = blockIdx.x * 128;

    float acc[2][8][4] = {};
    hmma_loop(sm, (const char*)(Ae + (size_t)m0 * 1536),
                  (const char*)(Be + (size_t)n0 * 1536),
              3072, 3072, 24, tid, acc);

    #pragma unroll
    for (int mi = 0; mi < 2; mi++) {
        int m = m0 + wm * 32 + mi * 16 + (lane >> 2);
        #pragma unroll
        for (int half = 0; half < 2; half++) {
            int mr = m + half * 8;
            int bidx = mr >> 11, npt = mr & 2047;
            size_t obase = ((size_t)bidx << 10) * NPTS + npt;
            #pragma unroll
            for (int nj = 0; nj < 8; nj++) {
                int col = n0 + wn * 64 + nj * 8 + (lane & 3) * 2;
                float g0 = __ldg(&g[col]), g1 = __ldg(&g[col + 1]);
                float b0 = __ldg(&bias[col]), b1 = __ldg(&bias[col + 1]);
                float z0 = fmaf(acc[mi][nj][half * 2],     g0, b0);
                float z1 = fmaf(acc[mi][nj][half * 2 + 1], g1, b1);
                out[obase + (size_t)col * NPTS]       = z0 >= 0.f ? z0 : NEG_SLOPE * z0;
                out[obase + (size_t)(col + 1) * NPTS] = z1 >= 0.f ? z1 : NEG_SLOPE * z1;
            }
        }
    }
}

// ---------------- bf16x3 expansion kernels ----------------------------------
__global__ void expand_gram(const float* __restrict__ X, __nv_bfloat16* __restrict__ Ae,
                            __nv_bfloat16* __restrict__ Be, int K, int Kexp) {
    long long i = (long long)blockIdx.x * 256 + threadIdx.x;
    if (i >= (long long)NB * Kexp) return;
    int m = (int)(i / Kexp), k = (int)(i - (long long)m * Kexp);
    int t = (k < K) ? 0 : (k < 2 * K) ? 1 : (k < 3 * K) ? 2 : 3;
    __nv_bfloat16 av, bv;
    if (t == 3) { av = __float2bfloat16(0.f); bv = av; }
    else {
        float v = X[(size_t)m * K + (k - t * K)];
        __nv_bfloat16 hi = __float2bfloat16(v);
        __nv_bfloat16 lo = __float2bfloat16(v - __bfloat162float(hi));
        av = (t == 2) ? lo : hi;
        bv = (t == 1) ? lo : hi;
    }
    Ae[i] = av; Be[i] = bv;
}

__global__ void expand_cat(const float* __restrict__ X1, const float* __restrict__ X2,
                           const float* __restrict__ X3, const float* __restrict__ X4,
                           __nv_bfloat16* __restrict__ Ae) {
    long long i = (long long)blockIdx.x * 256 + threadIdx.x;   // NB*1536
    int m = (int)(i / 1536);
    int k = (int)(i - (long long)m * 1536);
    int t = k >> 9, k0 = k & 511;
    float v;
    if (k0 < 64)       v = X1[(size_t)m * 64 + k0];
    else if (k0 < 128) v = X2[(size_t)m * 64 + k0 - 64];
    else if (k0 < 256) v = X3[(size_t)m * 128 + k0 - 128];
    else               v = X4[(size_t)m * 256 + k0 - 256];
    __nv_bfloat16 hi = __float2bfloat16(v);
    Ae[i] = (t == 2) ? __float2bfloat16(v - __bfloat162float(hi)) : hi;
}

__global__ void expand_w5(const float* __restrict__ W, __nv_bfloat16* __restrict__ Be) {
    long long i = (long long)blockIdx.x * 256 + threadIdx.x;   // 1024*1536
    int n = (int)(i / 1536);
    int k = (int)(i - (long long)n * 1536);
    int t = k >> 9, k0 = k & 511;
    float v = W[(size_t)k0 * 1024 + n];
    __nv_bfloat16 hi = __float2bfloat16(v);
    Be[i] = (t == 1) ? __float2bfloat16(v - __bfloat162float(hi)) : hi;
}

// ---------------- squared norms ----------------------------------------------
__global__ void xx_kernel(const float* __restrict__ X, float* __restrict__ xx, int C) {
    int gw = (blockIdx.x * blockDim.x + threadIdx.x) >> 5;
    int lane = threadIdx.x & 31;
    if (gw >= NB) return;
    const float* row = X + (size_t)gw * C;
    float s = 0.f;
    for (int c = lane; c < C; c += 32) { float v = row[c]; s += v * v; }
    #pragma unroll
    for (int o = 16; o > 0; o >>= 1) s += __shfl_xor_sync(0xFFFFFFFFu, s, o);
    if (lane == 0) xx[gw] = s;
}

// ---------------- generic SIMT C = A @ B (for PC) ----------------------------
__global__ void __launch_bounds__(256, 2) gemm_nn(const float* __restrict__ A,
                                                  const float* __restrict__ B,
                                                  float* __restrict__ Cout,
                                                  int N, int Kdim) {
    __shared__ float As[2][BK][BM + 4];
    __shared__ float Bs[2][BK][BN + 4];
    int tid = threadIdx.x;
    int m0 = blockIdx.y * BM, n0 = blockIdx.x * BN;
    int tm = tid >> 4, tn = tid & 15;
    int la_m = tid >> 3, la_k = tid & 7;
    int lb_k = tid >> 7, lb_n = tid & 127;
    float acc[8][8] = {};
    float ra[4], rb[4];
    int kIters = (Kdim + BK - 1) / BK;
    #pragma unroll
    for (int i = 0; i < 4; i++) {
        int m = la_m + 32 * i;
        ra[i] = (la_k < Kdim) ? A[(size_t)(m0 + m) * Kdim + la_k] : 0.f;
        int kb = lb_k + 2 * i;
        rb[i] = (kb < Kdim) ? B[(size_t)kb * N + n0 + lb_n] : 0.f;
    }
    #pragma unroll
    for (int i = 0; i < 4; i++) {
        As[0][la_k][la_m + 32 * i] = ra[i];
        Bs[0][lb_k + 2 * i][lb_n] = rb[i];
    }
    __syncthreads();
    int buf = 0;
    for (int it = 0; it < kIters; ++it) {
        if (it + 1 < kIters) {
            int k0n = (it + 1) * BK;
            #pragma unroll
            for (int i = 0; i < 4; i++) {
                int m = la_m + 32 * i;
                int ka = k0n + la_k;
                ra[i] = (ka < Kdim) ? A[(size_t)(m0 + m) * Kdim + ka] : 0.f;
                int kb = k0n + lb_k + 2 * i;
                rb[i] = (kb < Kdim) ? B[(size_t)kb * N + n0 + lb_n] : 0.f;
            }
        }
        #pragma unroll
        for (int k = 0; k < BK; k++) {
            float4 A0v = *(const float4*)&As[buf][k][tm * 8];
            float4 A1v = *(const float4*)&As[buf][k][tm * 8 + 4];
            float4 B0v = *(const float4*)&Bs[buf][k][tn * 8];
            float4 B1v = *(const float4*)&Bs[buf][k][tn * 8 + 4];
            float av[8] = {A0v.x, A0v.y, A0v.z, A0v.w, A1v.x, A1v.y, A1v.z, A1v.w};
            float bv[8] = {B0v.x, B0v.y, B0v.z, B0v.w, B1v.x, B1v.y, B1v.z, B1v.w};
            #pragma unroll
            for (int ii = 0; ii < 8; ii++)
                #pragma unroll
                for (int jj = 0; jj < 8; jj++)
                    acc[ii][jj] = fmaf(av[ii], bv[jj], acc[ii][jj]);
        }
        if (it + 1 < kIters) {
            #pragma unroll
            for (int i = 0; i < 4; i++) {
                As[buf ^ 1][la_k][la_m + 32 * i] = ra[i];
                Bs[buf ^ 1][lb_k + 2 * i][lb_n] = rb[i];
            }
        }
        __syncthreads();
        buf ^= 1;
    }
    #pragma unroll
    for (int ii = 0; ii < 8; ii++) {
        size_t p = (size_t)(m0 + tm * 8 + ii) * N + n0 + tn * 8;
        *(float4*)&Cout[p]     = make_float4(acc[ii][0], acc[ii][1], acc[ii][2], acc[ii][3]);
        *(float4*)&Cout[p + 4] = make_float4(acc[ii][4], acc[ii][5], acc[ii][6], acc[ii][7]);
    }
}

// ---------------- top-20: threshold select (redux tournament + compaction) ---
__device__ __forceinline__ uint32_t fmono(float f) {
    uint32_t bts = __float_as_uint(f);
    return (bts & 0x80000000u) ? ~bts : (bts | 0x80000000u);
}
#define CASD(x, y) { uint32_t hi = max(u[x], u[y]); uint32_t lo = min(u[x], u[y]); u[x] = hi; u[y] = lo; }
#define CASW(x, y) { uint32_t hi = max(w[x], w[y]); uint32_t lo = min(w[x], w[y]); w[x] = hi; w[y] = lo; }

__global__ void __launch_bounds__(256) topk_kernel(const float* __restrict__ negd,
                                                   int* __restrict__ idxout) {
    __shared__ uint32_t swv[160];
    __shared__ uint32_t s_T;
    __shared__ int s_ngt, s_neq;
    __shared__ int s_eq[64];
    int row = blockIdx.x, b = row >> 11, tid = threadIdx.x;
    int lane = tid & 31, wid = tid >> 5;
    const float* Grow = negd + (size_t)row * NPTS;
    float v[8]; uint32_t u[8];
    #pragma unroll
    for (int i = 0; i < 8; i++) { v[i] = __ldg(&Grow[tid + (i << 8)]); u[i] = fmono(v[i]); }
    // sort 8 desc (Batcher, 19 CAS)
    CASD(0,1) CASD(2,3) CASD(4,5) CASD(6,7)
    CASD(0,2) CASD(1,3) CASD(4,6) CASD(5,7)
    CASD(1,2) CASD(5,6)
    CASD(0,4) CASD(1,5) CASD(2,6) CASD(3,7)
    CASD(2,4) CASD(3,5)
    CASD(1,2) CASD(3,4) CASD(5,6)
    // phase 1: pop warp's 20 largest values
    #pragma unroll 1
    for (int r = 0; r < KNN; r++) {
        uint32_t m;
        asm volatile("redux.sync.max.u32 %0, %1, 0xffffffff;" : "=r"(m) : "r"(u[0]));
        uint32_t bal = __ballot_sync(0xffffffffu, u[0] == m);
        if (lane == (int)(__ffs(bal) - 1)) {
            #pragma unroll
            for (int i = 0; i < 7; i++) u[i] = u[i + 1];
            u[7] = 0;
        }
        if (lane == 0) swv[wid * KNN + r] = m;
    }
    if (tid == 0) { s_ngt = 0; s_neq = 0; }
    __syncthreads();
    // phase 2: warp 0 finds global 20th value T among 160 candidates
    if (wid == 0) {
        uint32_t w[5];
        #pragma unroll
        for (int t = 0; t < 5; t++) w[t] = swv[lane + (t << 5)];
        CASW(0,1) CASW(3,4) CASW(2,4) CASW(2,3) CASW(1,4)
        CASW(0,3) CASW(0,2) CASW(1,3) CASW(1,2)
        uint32_t T = 0;
        #pragma unroll 1
        for (int r = 0; r < KNN; r++) {
            asm volatile("redux.sync.max.u32 %0, %1, 0xffffffff;" : "=r"(T) : "r"(w[0]));
            uint32_t bal = __ballot_sync(0xffffffffu, w[0] == T);
            if (lane == (int)(__ffs(bal) - 1)) {
                w[0] = w[1]; w[1] = w[2]; w[2] = w[3]; w[3] = w[4]; w[4] = 0;
            }
        }
        if (lane == 0) s_T = T;
    }
    __syncthreads();
    uint32_t T = s_T;
    int* outp = idxout + row * KNN;
    // compaction: strictly-greater written unordered; equals by smallest index
    #pragma unroll
    for (int i = 0; i < 8; i++) {
        uint32_t ui = fmono(v[i]);
        if (ui > T) {
            int p = atomicAdd(&s_ngt, 1);
            outp[p] = (b << 11) + tid + (i << 8);
        } else if (ui == T) {
            int p = atomicAdd(&s_neq, 1);
            if (p < 64) s_eq[p] = tid + (i << 8);
        }
    }
    __syncthreads();
    if (tid == 0) {
        int ngt = s_ngt;
        int neq = s_neq < 64 ? s_neq : 64;
        int need = KNN - ngt;
        for (int t = 0; t < need; t++) {
            int bvv = 0x7fffffff, bi = 0;
            for (int q = 0; q < neq; q++)
                if (s_eq[q] < bvv) { bvv = s_eq[q]; bi = q; }
            s_eq[bi] = 0x7fffffff;
            outp[ngt + t] = (b << 11) + bvv;
        }
    }
}

// ---------------- gather + max/min + epilogue --------------------------------
__global__ void gathermax_kernel(const float* __restrict__ PC,
                                 const int* __restrict__ idx,
                                 const float* __restrict__ g,
                                 const float* __restrict__ bias,
                                 float* __restrict__ Xout, int cl) {
    int cout = 1 << cl;
    int i = blockIdx.x * 256 + threadIdx.x;
    int n = i >> cl, d = i & (cout - 1);
    int ld = cout << 1;
    const int* ip = idx + n * KNN;
    float mx = -FLT_MAX, mn = FLT_MAX;
    #pragma unroll
    for (int k = 0; k < KNN; k++) {
        float v = __ldg(&PC[(size_t)__ldg(&ip[k]) * ld + d]);
        mx = fmaxf(mx, v); mn = fminf(mn, v);
    }
    float Cc = PC[(size_t)n * ld + cout + d];
    float gd = g[d], bd = bias[d];
    float z = (gd >= 0.f ? mx : mn) + Cc;
    float h = fmaf(gd, z, bd);
    Xout[i] = h >= 0.f ? h : NEG_SLOPE * h;
}

// ---------------- combined weight: [W_a | W_b - W_a] -------------------------
__global__ void wcomb_kernel(const float* __restrict__ W, float* __restrict__ Wc,
                             int cin, int cout) {
    int i = blockIdx.x * 256 + threadIdx.x;
    int tot = cin * 2 * cout;
    if (i >= tot) return;
    int twoc = 2 * cout;
    int c = i / twoc, j = i - c * twoc;
    float v;
    if (j < cout) v = W[c * cout + j];
    else { int dd = j - cout; v = W[(cin + c) * cout + dd] - W[c * cout + dd]; }
    Wc[i] = v;
}

// ---------------- host launch -------------------------------------------------
extern "C" void kernel_launch(void* const* d_in, const int* in_sizes, int n_in,
                              void* d_out, int out_size) {
    (void)in_sizes; (void)n_in; (void)out_size;
    const float* pts = (const float*)d_in[0];
    const float* W[5]; const float* gg[5]; const float* bb[5];
    for (int i = 0; i < 5; i++) {
        W[i]  = (const float*)d_in[1 + 3 * i];
        gg[i] = (const float*)d_in[2 + 3 * i];
        bb[i] = (const float*)d_in[3 + 3 * i];
    }
    float* out = (float*)d_out;

    float *X1, *X2, *X3, *X4, *PC, *G, *XX, *WC; int* IDX;
    __nv_bfloat16 *XA, *XB, *CE, *WE;
    cudaGetSymbolAddress((void**)&X1, g_X1);
    cudaGetSymbolAddress((void**)&X2, g_X2);
    cudaGetSymbolAddress((void**)&X3, g_X3);
    cudaGetSymbolAddress((void**)&X4, g_X4);
    cudaGetSymbolAddress((void**)&PC, g_PC);
    cudaGetSymbolAddress((void**)&G,  g_G);
    cudaGetSymbolAddress((void**)&XX, g_xx);
    cudaGetSymbolAddress((void**)&WC, g_Wcomb);
    cudaGetSymbolAddress((void**)&IDX, g_idx);
    cudaGetSymbolAddress((void**)&XA, g_XexpA);
    cudaGetSymbolAddress((void**)&XB, g_XexpB);
    cudaGetSymbolAddress((void**)&CE, g_CATexp);
    cudaGetSymbolAddress((void**)&WE, g_W5exp);

    cudaFuncSetAttribute(gram_hmma, cudaFuncAttributeMaxDynamicSharedMemorySize, GR_SMEM);
    cudaFuncSetAttribute(w5_hmma,   cudaFuncAttributeMaxDynamicSharedMemorySize, W5_SMEM);

    struct L { const float* Xin; int cin, cout, cl, kexp; float* Xout; };
    L layers[4] = {
        { pts, 3,   64,  6, 64,  X1 },
        { X1,  64,  64,  6, 192, X2 },
        { X2,  64,  128, 7, 192, X3 },
        { X3,  128, 256, 8, 384, X4 },
    };
    for (int li = 0; li < 4; li++) {
        const L& l = layers[li];
        xx_kernel<<<NB / 8, 256>>>(l.Xin, XX, l.cin);
        long long etot = (long long)NB * l.kexp;
        expand_gram<<<(unsigned)((etot + 255) / 256), 256>>>(l.Xin, XA, XB, l.cin, l.kexp);
        gram_hmma<<<dim3(136, 1, BATCH), 256, GR_SMEM>>>(XA, XB, XX, G, l.kexp);
        topk_kernel<<<NB, 256>>>(G, IDX);
        int tot = l.cin * 2 * l.cout;
        wcomb_kernel<<<(tot + 255) / 256, 256>>>(W[li], WC, l.cin, l.cout);
        gemm_nn<<<dim3((2 * l.cout) / BN, NB / BM), 256>>>(l.Xin, WC, PC, 2 * l.cout, l.cin);
        gathermax_kernel<<<(NB * l.cout) / 256, 256>>>(PC, IDX, gg[li], bb[li], l.Xout, l.cl);
    }
    expand_cat<<<(unsigned)(((long long)NB * 1536 + 255) / 256), 256>>>(X1, X2, X3, X4, CE);
    expand_w5<<<(1024 * 1536) / 256, 256>>>(W[4], WE);
    w5_hmma<<<dim3(1024 / 128, NB / 128), 256, W5_SMEM>>>(CE, WE, gg[4], bb[4], out);
}

// round 14
// speedup vs baseline: 2.7079x; 1.0175x over previous
#include <cuda_runtime.h>
#include <cuda_bf16.h>
#include <float.h>
#include <stdint.h>

#define NB    16384
#define NPTS  2048
#define BATCH 8
#define KNN   20
#define NEG_SLOPE 0.2f

// ---------------- scratch (device globals) ----------------------------------
__device__ float g_X1[NB * 64];
__device__ float g_X2[NB * 64];
__device__ float g_X3[NB * 128];
__device__ float g_X4[NB * 256];
__device__ float g_PC[NB * 512];
__device__ float g_G[(size_t)BATCH * NPTS * NPTS];   // holds negd
__device__ float g_xx[NB];
__device__ int   g_idx[NB * KNN];
__device__ float g_Wcomb[128 * 512];
__device__ __nv_bfloat16 g_XexpA[(size_t)NB * 384];  // 3-term A-form (Gram)
__device__ __nv_bfloat16 g_XexpB[(size_t)NB * 384];  // 3-term B-form (Gram)
__device__ __nv_bfloat16 g_CATexp[(size_t)NB * 1536];
__device__ __nv_bfloat16 g_W5exp[(size_t)1024 * 1536];

// ======================= warp-MMA helpers (plain PTX, sm_80+) ================
__device__ __forceinline__ uint32_t smem_u32(const void* p) {
    uint32_t a;
    asm("{ .reg .u64 t; cvta.to.shared.u64 t, %1; cvt.u32.u64 %0, t; }"
        : "=r"(a) : "l"(p));
    return a;
}

#define SWZ(o) ((o) ^ (((o) >> 3) & 0x70))

#define LDSM4(r, a) \
    asm volatile("ldmatrix.sync.aligned.m8n8.x4.shared.b16 {%0,%1,%2,%3}, [%4];" \
        : "=r"((r)[0]), "=r"((r)[1]), "=r"((r)[2]), "=r"((r)[3]) : "r"(a))

#define MMA16816(d, a, b0, b1) \
    asm volatile("mma.sync.aligned.m16n8k16.row.col.f32.bf16.bf16.f32 " \
        "{%0,%1,%2,%3},{%4,%5,%6,%7},{%8,%9},{%0,%1,%2,%3};" \
        : "+f"((d)[0]), "+f"((d)[1]), "+f"((d)[2]), "+f"((d)[3]) \
        : "r"((a)[0]), "r"((a)[1]), "r"((a)[2]), "r"((a)[3]), "r"(b0), "r"(b1))

#define STAGE_B 16384                      // 128 rows x 128 bytes
#define W5_SMEM (4 * STAGE_B + 128)        // 2 stages x 2 operands
#define TILE_PITCH 133
#define GR_SMEM (128 * TILE_PITCH * 4 + 256)  // transpose tile dominates

// mainloop: acc += A(128 x 64*kc) * B(128 x 64*kc)^T, both row-major bf16
__device__ __forceinline__ void hmma_loop(char* sm, const char* Ag, const char* Bg,
                                          size_t strA, size_t strB, int kchunks,
                                          int tid, float acc[2][8][4]) {
    char* sA = sm;
    char* sB = sm + 2 * STAGE_B;
    int lane = tid & 31, wid = tid >> 5;
    int wm = wid & 3, wn = wid >> 2;
    int r = tid >> 3, cbyte = (tid & 7) * 16;
    #pragma unroll
    for (int i = 0; i < 4; i++) {
        int row = r + 32 * i;
        *(uint4*)(sA + SWZ(row * 128 + cbyte)) = *(const uint4*)(Ag + (size_t)row * strA + cbyte);
        *(uint4*)(sB + SWZ(row * 128 + cbyte)) = *(const uint4*)(Bg + (size_t)row * strB + cbyte);
    }
    __syncthreads();
    uint32_t sA32 = smem_u32(sA), sB32 = smem_u32(sB);
    int buf = 0;
    for (int c = 0; c < kchunks; c++) {
        uint4 pa[4], pb[4];
        if (c + 1 < kchunks) {
            const char* An = Ag + (size_t)(c + 1) * 128;
            const char* Bn = Bg + (size_t)(c + 1) * 128;
            #pragma unroll
            for (int i = 0; i < 4; i++) {
                int row = r + 32 * i;
                pa[i] = *(const uint4*)(An + (size_t)row * strA + cbyte);
                pb[i] = *(const uint4*)(Bn + (size_t)row * strB + cbyte);
            }
        }
        uint32_t aB = sA32 + buf * STAGE_B, bB = sB32 + buf * STAGE_B;
        #pragma unroll
        for (int ks = 0; ks < 4; ks++) {
            uint32_t a[2][4], b[4][4];
            #pragma unroll
            for (int mi = 0; mi < 2; mi++) {
                int row = wm * 32 + mi * 16 + (lane & 15);
                int off = row * 128 + ks * 32 + ((lane >> 4) << 4);
                LDSM4(a[mi], aB + SWZ(off));
            }
            #pragma unroll
            for (int np = 0; np < 4; np++) {
                int row = wn * 64 + np * 16 + ((lane >> 4) << 3) + (lane & 7);
                int off = row * 128 + ks * 32 + (((lane >> 3) & 1) << 4);
                LDSM4(b[np], bB + SWZ(off));
            }
            #pragma unroll
            for (int mi = 0; mi < 2; mi++)
                #pragma unroll
                for (int nj = 0; nj < 8; nj++)
                    MMA16816(acc[mi][nj], a[mi], b[nj >> 1][(nj & 1) * 2], b[nj >> 1][(nj & 1) * 2 + 1]);
        }
        if (c + 1 < kchunks) {
            char* dA = sA + (buf ^ 1) * STAGE_B;
            char* dB = sB + (buf ^ 1) * STAGE_B;
            #pragma unroll
            for (int i = 0; i < 4; i++) {
                int row = r + 32 * i;
                *(uint4*)(dA + SWZ(row * 128 + cbyte)) = pa[i];
                *(uint4*)(dB + SWZ(row * 128 + cbyte)) = pb[i];
            }
            __syncthreads();
            buf ^= 1;
        }
    }
}

// --------- Gram (triangular blocks): negd = 2*X@X^T - xx_m - xx_n ------------
__global__ void __launch_bounds__(256) gram_hmma(const __nv_bfloat16* __restrict__ Ae,
                                                 const __nv_bfloat16* __restrict__ Be,
                                                 const float* __restrict__ xx,
                                                 float* __restrict__ negd, int Kexp) {
    extern __shared__ char dsm[];
    uint32_t sb = smem_u32(dsm);
    char* sm = dsm + (((sb + 127) & ~127u) - sb);
    int tid = threadIdx.x, lane = tid & 31, wid = tid >> 5;
    int wm = wid & 3, wn = wid >> 2;
    int b = blockIdx.z;
    int rem = blockIdx.x, ti = 0;
    while (rem >= 16 - ti) { rem -= 16 - ti; ti++; }
    int tj = ti + rem;
    int m0 = ti * 128, n0 = tj * 128;

    float acc[2][8][4] = {};
    size_t str = (size_t)Kexp * 2;
    hmma_loop(sm, (const char*)(Ae + (size_t)(b * NPTS + m0) * Kexp),
                  (const char*)(Be + (size_t)(b * NPTS + n0) * Kexp),
              str, str, Kexp >> 6, tid, acc);

    const float* xxb = xx + b * NPTS;
    float* nd = negd + ((size_t)b << 22);
    float (*tile)[TILE_PITCH] = (float(*)[TILE_PITCH])sm;

    if (ti != tj) __syncthreads();

    #pragma unroll
    for (int mi = 0; mi < 2; mi++) {
        int lm0 = wm * 32 + mi * 16 + (lane >> 2);
        int rowa = m0 + lm0;
        float xm0 = __ldg(&xxb[rowa]), xm1 = __ldg(&xxb[rowa + 8]);
        #pragma unroll
        for (int nj = 0; nj < 8; nj++) {
            int ln = wn * 64 + nj * 8 + (lane & 3) * 2;
            int col = n0 + ln;
            float xn0 = __ldg(&xxb[col]), xn1 = __ldg(&xxb[col + 1]);
            float v00 = 2.f * acc[mi][nj][0] - xm0 - xn0;
            float v01 = 2.f * acc[mi][nj][1] - xm0 - xn1;
            float v10 = 2.f * acc[mi][nj][2] - xm1 - xn0;
            float v11 = 2.f * acc[mi][nj][3] - xm1 - xn1;
            *(float2*)&nd[(size_t)rowa * NPTS + col]       = make_float2(v00, v01);
            *(float2*)&nd[(size_t)(rowa + 8) * NPTS + col] = make_float2(v10, v11);
            if (ti != tj) {
                tile[lm0][ln]         = v00;
                tile[lm0][ln + 1]     = v01;
                tile[lm0 + 8][ln]     = v10;
                tile[lm0 + 8][ln + 1] = v11;
            }
        }
    }
    if (ti != tj) {
        __syncthreads();
        int nn = tid >> 1;
        int mmBase = (tid & 1) * 64;
        size_t gbase = (size_t)(n0 + nn) * NPTS + m0 + mmBase;
        #pragma unroll
        for (int k4 = 0; k4 < 16; k4++) {
            int mm = mmBase + k4 * 4;
            float4 w = make_float4(tile[mm][nn], tile[mm + 1][nn],
                                   tile[mm + 2][nn], tile[mm + 3][nn]);
            *(float4*)&nd[gbase + k4 * 4] = w;
        }
    }
}

// --------- W5: out = lrelu(cat@W5 * g + b), transposed store -----------------
__global__ void __launch_bounds__(256) w5_hmma(const __nv_bfloat16* __restrict__ Ae,
                                               const __nv_bfloat16* __restrict__ Be,
                                               const float* __restrict__ g,
                                               const float* __restrict__ bias,
                                               float* __restrict__ out) {
    extern __shared__ char dsm[];
    uint32_t sb = smem_u32(dsm);
    char* sm = dsm + (((sb + 127) & ~127u) - sb);
    int tid = threadIdx.x, lane = tid & 31, wid = tid >> 5;
    int wm = wid & 3, wn = wid >> 2;
    int m0 = blockIdx.y * 128, n0 = blockIdx.x * 128;

    float acc[2][8][4] = {};
    hmma_loop(sm, (const char*)(Ae + (size_t)m0 * 1536),
                  (const char*)(Be + (size_t)n0 * 1536),
              3072, 3072, 24, tid, acc);

    #pragma unroll
    for (int mi = 0; mi < 2; mi++) {
        int m = m0 + wm * 32 + mi * 16 + (lane >> 2);
        #pragma unroll
        for (int half = 0; half < 2; half++) {
            int mr = m + half * 8;
            int bidx = mr >> 11, npt = mr & 2047;
            size_t obase = ((size_t)bidx << 10) * NPTS + npt;
            #pragma unroll
            for (int nj = 0; nj < 8; nj++) {
                int col = n0 + wn * 64 + nj * 8 + (lane & 3) * 2;
                float g0 = __ldg(&g[col]), g1 = __ldg(&g[col + 1]);
                float b0 = __ldg(&bias[col]), b1 = __ldg(&bias[col + 1]);
                float z0 = fmaf(acc[mi][nj][half * 2],     g0, b0);
                float z1 = fmaf(acc[mi][nj][half * 2 + 1], g1, b1);
                out[obase + (size_t)col * NPTS]       = z0 >= 0.f ? z0 : NEG_SLOPE * z0;
                out[obase + (size_t)(col + 1) * NPTS] = z1 >= 0.f ? z1 : NEG_SLOPE * z1;
            }
        }
    }
}

// ---------------- bf16x3 expansion kernels (Gram only) -----------------------
__global__ void expand_gram(const float* __restrict__ X, __nv_bfloat16* __restrict__ Ae,
                            __nv_bfloat16* __restrict__ Be, int K, int Kexp) {
    long long i = (long long)blockIdx.x * 256 + threadIdx.x;
    if (i >= (long long)NB * Kexp) return;
    int m = (int)(i / Kexp), k = (int)(i - (long long)m * Kexp);
    int t = (k < K) ? 0 : (k < 2 * K) ? 1 : (k < 3 * K) ? 2 : 3;
    __nv_bfloat16 av, bv;
    if (t == 3) { av = __float2bfloat16(0.f); bv = av; }
    else {
        float v = X[(size_t)m * K + (k - t * K)];
        __nv_bfloat16 hi = __float2bfloat16(v);
        __nv_bfloat16 lo = __float2bfloat16(v - __bfloat162float(hi));
        av = (t == 2) ? lo : hi;
        bv = (t == 1) ? lo : hi;
    }
    Ae[i] = av; Be[i] = bv;
}

__global__ void expand_cat(const float* __restrict__ X1, const float* __restrict__ X2,
                           const float* __restrict__ X3, const float* __restrict__ X4,
                           __nv_bfloat16* __restrict__ Ae) {
    long long i = (long long)blockIdx.x * 256 + threadIdx.x;   // NB*1536
    int m = (int)(i / 1536);
    int k = (int)(i - (long long)m * 1536);
    int t = k >> 9, k0 = k & 511;
    float v;
    if (k0 < 64)       v = X1[(size_t)m * 64 + k0];
    else if (k0 < 128) v = X2[(size_t)m * 64 + k0 - 64];
    else if (k0 < 256) v = X3[(size_t)m * 128 + k0 - 128];
    else               v = X4[(size_t)m * 256 + k0 - 256];
    __nv_bfloat16 hi = __float2bfloat16(v);
    Ae[i] = (t == 2) ? __float2bfloat16(v - __bfloat162float(hi)) : hi;
}

__global__ void expand_w5(const float* __restrict__ W, __nv_bfloat16* __restrict__ Be) {
    long long i = (long long)blockIdx.x * 256 + threadIdx.x;   // 1024*1536
    int n = (int)(i / 1536);
    int k = (int)(i - (long long)n * 1536);
    int t = k >> 9, k0 = k & 511;
    float v = W[(size_t)k0 * 1024 + n];
    __nv_bfloat16 hi = __float2bfloat16(v);
    Be[i] = (t == 1) ? __float2bfloat16(v - __bfloat162float(hi)) : hi;
}

// ---------------- squared norms ----------------------------------------------
__global__ void xx_kernel(const float* __restrict__ X, float* __restrict__ xx, int C) {
    int gw = (blockIdx.x * blockDim.x + threadIdx.x) >> 5;
    int lane = threadIdx.x & 31;
    if (gw >= NB) return;
    const float* row = X + (size_t)gw * C;
    float s = 0.f;
    for (int c = lane; c < C; c += 32) { float v = row[c]; s += v * v; }
    #pragma unroll
    for (int o = 16; o > 0; o >>= 1) s += __shfl_xor_sync(0xFFFFFFFFu, s, o);
    if (lane == 0) xx[gw] = s;
}

// ---------------- PC: fp32 SIMT 64x64 tiles, ascending-k (bit-exact) ---------
__global__ void __launch_bounds__(256) gemm_nn64(const float* __restrict__ A,
                                                 const float* __restrict__ B,
                                                 float* __restrict__ Cout,
                                                 int N, int Kdim) {
    __shared__ float As[2][8][68];   // [k][m]
    __shared__ float Bs[2][8][68];   // [k][n]
    int tid = threadIdx.x;
    int m0 = blockIdx.y * 64, n0 = blockIdx.x * 64;
    int tm = tid >> 4, tn = tid & 15;
    int la_m = tid >> 3, la_k = tid & 7;      // A: 64x8, 2 rows/thread
    int lb_k = tid >> 6, lb_n = tid & 63;     // B: 8x64, 2 k/thread
    float acc[4][4] = {};
    float ra[2], rb[2];
    int kIters = (Kdim + 7) / 8;
    #pragma unroll
    for (int j = 0; j < 2; j++) {
        ra[j] = (la_k < Kdim) ? A[(size_t)(m0 + la_m + 32 * j) * Kdim + la_k] : 0.f;
        int kb = lb_k + 4 * j;
        rb[j] = (kb < Kdim) ? B[(size_t)kb * N + n0 + lb_n] : 0.f;
    }
    #pragma unroll
    for (int j = 0; j < 2; j++) {
        As[0][la_k][la_m + 32 * j] = ra[j];
        Bs[0][lb_k + 4 * j][lb_n] = rb[j];
    }
    __syncthreads();
    int buf = 0;
    for (int it = 0; it < kIters; ++it) {
        if (it + 1 < kIters) {
            int k0n = (it + 1) * 8;
            #pragma unroll
            for (int j = 0; j < 2; j++) {
                int ka = k0n + la_k;
                ra[j] = (ka < Kdim) ? A[(size_t)(m0 + la_m + 32 * j) * Kdim + ka] : 0.f;
                int kb = k0n + lb_k + 4 * j;
                rb[j] = (kb < Kdim) ? B[(size_t)kb * N + n0 + lb_n] : 0.f;
            }
        }
        #pragma unroll
        for (int k = 0; k < 8; k++) {
            float4 a4 = *(const float4*)&As[buf][k][tm * 4];
            float4 b4 = *(const float4*)&Bs[buf][k][tn * 4];
            float av[4] = {a4.x, a4.y, a4.z, a4.w};
            float bv[4] = {b4.x, b4.y, b4.z, b4.w};
            #pragma unroll
            for (int ii = 0; ii < 4; ii++)
                #pragma unroll
                for (int jj = 0; jj < 4; jj++)
                    acc[ii][jj] = fmaf(av[ii], bv[jj], acc[ii][jj]);
        }
        if (it + 1 < kIters) {
            #pragma unroll
            for (int j = 0; j < 2; j++) {
                As[buf ^ 1][la_k][la_m + 32 * j] = ra[j];
                Bs[buf ^ 1][lb_k + 4 * j][lb_n] = rb[j];
            }
        }
        __syncthreads();
        buf ^= 1;
    }
    #pragma unroll
    for (int ii = 0; ii < 4; ii++) {
        *(float4*)&Cout[(size_t)(m0 + tm * 4 + ii) * N + n0 + tn * 4] =
            make_float4(acc[ii][0], acc[ii][1], acc[ii][2], acc[ii][3]);
    }
}

// ---------------- top-20: threshold select (redux tournament + compaction) ---
__device__ __forceinline__ uint32_t fmono(float f) {
    uint32_t bts = __float_as_uint(f);
    return (bts & 0x80000000u) ? ~bts : (bts | 0x80000000u);
}
#define CASD(x, y) { uint32_t hi = max(u[x], u[y]); uint32_t lo = min(u[x], u[y]); u[x] = hi; u[y] = lo; }
#define CASW(x, y) { uint32_t hi = max(w[x], w[y]); uint32_t lo = min(w[x], w[y]); w[x] = hi; w[y] = lo; }

__global__ void __launch_bounds__(256) topk_kernel(const float* __restrict__ negd,
                                                   int* __restrict__ idxout) {
    __shared__ uint32_t swv[160];
    __shared__ uint32_t s_T;
    __shared__ int s_ngt, s_neq;
    __shared__ int s_eq[64];
    int row = blockIdx.x, b = row >> 11, tid = threadIdx.x;
    int lane = tid & 31, wid = tid >> 5;
    const float* Grow = negd + (size_t)row * NPTS;
    float v[8]; uint32_t u[8];
    #pragma unroll
    for (int i = 0; i < 8; i++) { v[i] = __ldg(&Grow[tid + (i << 8)]); u[i] = fmono(v[i]); }
    CASD(0,1) CASD(2,3) CASD(4,5) CASD(6,7)
    CASD(0,2) CASD(1,3) CASD(4,6) CASD(5,7)
    CASD(1,2) CASD(5,6)
    CASD(0,4) CASD(1,5) CASD(2,6) CASD(3,7)
    CASD(2,4) CASD(3,5)
    CASD(1,2) CASD(3,4) CASD(5,6)
    #pragma unroll 1
    for (int r = 0; r < KNN; r++) {
        uint32_t m;
        asm volatile("redux.sync.max.u32 %0, %1, 0xffffffff;" : "=r"(m) : "r"(u[0]));
        uint32_t bal = __ballot_sync(0xffffffffu, u[0] == m);
        if (lane == (int)(__ffs(bal) - 1)) {
            #pragma unroll
            for (int i = 0; i < 7; i++) u[i] = u[i + 1];
            u[7] = 0;
        }
        if (lane == 0) swv[wid * KNN + r] = m;
    }
    if (tid == 0) { s_ngt = 0; s_neq = 0; }
    __syncthreads();
    if (wid == 0) {
        uint32_t w[5];
        #pragma unroll
        for (int t = 0; t < 5; t++) w[t] = swv[lane + (t << 5)];
        CASW(0,1) CASW(3,4) CASW(2,4) CASW(2,3) CASW(1,4)
        CASW(0,3) CASW(0,2) CASW(1,3) CASW(1,2)
        uint32_t T = 0;
        #pragma unroll 1
        for (int r = 0; r < KNN; r++) {
            asm volatile("redux.sync.max.u32 %0, %1, 0xffffffff;" : "=r"(T) : "r"(w[0]));
            uint32_t bal = __ballot_sync(0xffffffffu, w[0] == T);
            if (lane == (int)(__ffs(bal) - 1)) {
                w[0] = w[1]; w[1] = w[2]; w[2] = w[3]; w[3] = w[4]; w[4] = 0;
            }
        }
        if (lane == 0) s_T = T;
    }
    __syncthreads();
    uint32_t T = s_T;
    int* outp = idxout + row * KNN;
    #pragma unroll
    for (int i = 0; i < 8; i++) {
        uint32_t ui = fmono(v[i]);
        if (ui > T) {
            int p = atomicAdd(&s_ngt, 1);
            outp[p] = (b << 11) + tid + (i << 8);
        } else if (ui == T) {
            int p = atomicAdd(&s_neq, 1);
            if (p < 64) s_eq[p] = tid + (i << 8);
        }
    }
    __syncthreads();
    if (tid == 0) {
        int ngt = s_ngt;
        int neq = s_neq < 64 ? s_neq : 64;
        int need = KNN - ngt;
        for (int t = 0; t < need; t++) {
            int bvv = 0x7fffffff, bi = 0;
            for (int q = 0; q < neq; q++)
                if (s_eq[q] < bvv) { bvv = s_eq[q]; bi = q; }
            s_eq[bi] = 0x7fffffff;
            outp[ngt + t] = (b << 11) + bvv;
        }
    }
}

// ---------------- gather + max/min + epilogue (float4) -----------------------
__global__ void gathermax4_kernel(const float* __restrict__ PC,
                                  const int* __restrict__ idx,
                                  const float* __restrict__ g,
                                  const float* __restrict__ bias,
                                  float* __restrict__ Xout, int cl) {
    int cout = 1 << cl;
    int i = blockIdx.x * 256 + threadIdx.x;      // over NB*cout/4
    int n = i >> (cl - 2);
    int d = (i & ((cout >> 2) - 1)) << 2;
    int ld = cout << 1;
    const int* ip = idx + n * KNN;
    float4 mx = make_float4(-FLT_MAX, -FLT_MAX, -FLT_MAX, -FLT_MAX);
    float4 mn = make_float4(FLT_MAX, FLT_MAX, FLT_MAX, FLT_MAX);
    #pragma unroll
    for (int k = 0; k < KNN; k++) {
        float4 v = *(const float4*)&PC[(size_t)__ldg(&ip[k]) * ld + d];
        mx.x = fmaxf(mx.x, v.x); mn.x = fminf(mn.x, v.x);
        mx.y = fmaxf(mx.y, v.y); mn.y = fminf(mn.y, v.y);
        mx.z = fmaxf(mx.z, v.z); mn.z = fminf(mn.z, v.z);
        mx.w = fmaxf(mx.w, v.w); mn.w = fminf(mn.w, v.w);
    }
    float4 Cc = *(const float4*)&PC[(size_t)n * ld + cout + d];
    float4 gd = *(const float4*)&g[d];
    float4 bd = *(const float4*)&bias[d];
    float4 o;
    float z;
    z = (gd.x >= 0.f ? mx.x : mn.x) + Cc.x; z = fmaf(gd.x, z, bd.x); o.x = z >= 0.f ? z : NEG_SLOPE * z;
    z = (gd.y >= 0.f ? mx.y : mn.y) + Cc.y; z = fmaf(gd.y, z, bd.y); o.y = z >= 0.f ? z : NEG_SLOPE * z;
    z = (gd.z >= 0.f ? mx.z : mn.z) + Cc.z; z = fmaf(gd.z, z, bd.z); o.z = z >= 0.f ? z : NEG_SLOPE * z;
    z = (gd.w >= 0.f ? mx.w : mn.w) + Cc.w; z = fmaf(gd.w, z, bd.w); o.w = z >= 0.f ? z : NEG_SLOPE * z;
    *(float4*)&Xout[(size_t)n * cout + d] = o;
}

// ---------------- combined weight: [W_a | W_b - W_a] -------------------------
__global__ void wcomb_kernel(const float* __restrict__ W, float* __restrict__ Wc,
                             int cin, int cout) {
    int i = blockIdx.x * 256 + threadIdx.x;
    int tot = cin * 2 * cout;
    if (i >= tot) return;
    int twoc = 2 * cout;
    int c = i / twoc, j = i - c * twoc;
    float v;
    if (j < cout) v = W[c * cout + j];
    else { int dd = j - cout; v = W[(cin + c) * cout + dd] - W[c * cout + dd]; }
    Wc[i] = v;
}

// ---------------- host launch -------------------------------------------------
extern "C" void kernel_launch(void* const* d_in, const int* in_sizes, int n_in,
                              void* d_out, int out_size) {
    (void)in_sizes; (void)n_in; (void)out_size;
    const float* pts = (const float*)d_in[0];
    const float* W[5]; const float* gg[5]; const float* bb[5];
    for (int i = 0; i < 5; i++) {
        W[i]  = (const float*)d_in[1 + 3 * i];
        gg[i] = (const float*)d_in[2 + 3 * i];
        bb[i] = (const float*)d_in[3 + 3 * i];
    }
    float* out = (float*)d_out;

    float *X1, *X2, *X3, *X4, *PC, *G, *XX, *WC; int* IDX;
    __nv_bfloat16 *XA, *XB, *CE, *WE;
    cudaGetSymbolAddress((void**)&X1, g_X1);
    cudaGetSymbolAddress((void**)&X2, g_X2);
    cudaGetSymbolAddress((void**)&X3, g_X3);
    cudaGetSymbolAddress((void**)&X4, g_X4);
    cudaGetSymbolAddress((void**)&PC, g_PC);
    cudaGetSymbolAddress((void**)&G,  g_G);
    cudaGetSymbolAddress((void**)&XX, g_xx);
    cudaGetSymbolAddress((void**)&WC, g_Wcomb);
    cudaGetSymbolAddress((void**)&IDX, g_idx);
    cudaGetSymbolAddress((void**)&XA, g_XexpA);
    cudaGetSymbolAddress((void**)&XB, g_XexpB);
    cudaGetSymbolAddress((void**)&CE, g_CATexp);
    cudaGetSymbolAddress((void**)&WE, g_W5exp);

    cudaFuncSetAttribute(gram_hmma, cudaFuncAttributeMaxDynamicSharedMemorySize, GR_SMEM);
    cudaFuncSetAttribute(w5_hmma,   cudaFuncAttributeMaxDynamicSharedMemorySize, W5_SMEM);

    struct L { const float* Xin; int cin, cout, cl, kexp; float* Xout; };
    L layers[4] = {
        { pts, 3,   64,  6, 64,  X1 },
        { X1,  64,  64,  6, 192, X2 },
        { X2,  64,  128, 7, 192, X3 },
        { X3,  128, 256, 8, 384, X4 },
    };
    for (int li = 0; li < 4; li++) {
        const L& l = layers[li];
        xx_kernel<<<NB / 8, 256>>>(l.Xin, XX, l.cin);
        long long etot = (long long)NB * l.kexp;
        expand_gram<<<(unsigned)((etot + 255) / 256), 256>>>(l.Xin, XA, XB, l.cin, l.kexp);
        gram_hmma<<<dim3(136, 1, BATCH), 256, GR_SMEM>>>(XA, XB, XX, G, l.kexp);
        topk_kernel<<<NB, 256>>>(G, IDX);
        int N2 = 2 * l.cout;
        int tot = l.cin * N2;
        wcomb_kernel<<<(tot + 255) / 256, 256>>>(W[li], WC, l.cin, l.cout);
        gemm_nn64<<<dim3(N2 / 64, NB / 64), 256>>>(l.Xin, WC, PC, N2, l.cin);
        gathermax4_kernel<<<(NB * l.cout / 4) / 256, 256>>>(PC, IDX, gg[li], bb[li], l.Xout, l.cl);
    }
    expand_cat<<<(unsigned)(((long long)NB * 1536 + 255) / 256), 256>>>(X1, X2, X3, X4, CE);
    expand_w5<<<(1024 * 1536) / 256, 256>>>(W[4], WE);
    w5_hmma<<<dim3(1024 / 128, NB / 128), 256, W5_SMEM>>>(CE, WE, gg[4], bb[4], out);
}